// round 15
// baseline (speedup 1.0000x reference)
#include <cuda_runtime.h>
#include <cuda_fp16.h>
#include <cstdint>
#include <math.h>

#define S_LEN 2048
#define DIM 3072
#define HEADS 24
#define HEAD_DIM 128
#define MLP_H 12288
#define CAT_K (DIM + MLP_H)   // 15360
#define QKV_N (3 * DIM)       // 9216

// ---------------- scratch (device globals; no runtime allocs allowed) -------
#define ALN __align__(128)
__device__ ALN float g_emb[3 * DIM];
__device__ ALN float g_bqkv[QKV_N];
__device__ ALN float g_part[3 * S_LEN * DIM];
__device__ ALN __half g_nh[S_LEN * DIM];
__device__ ALN __half g_wqkv[QKV_N * DIM];
__device__ ALN __half g_wm[MLP_H * DIM];
__device__ ALN __half g_wo[DIM * CAT_K];
__device__ ALN __half g_mlp[S_LEN * MLP_H];
__device__ ALN __half g_attnh[S_LEN * DIM];
__device__ ALN __half g_qh[S_LEN * DIM];
__device__ ALN __half g_kh[S_LEN * DIM];
__device__ ALN __half g_vh[S_LEN * DIM];

// ---------------- PTX helpers ----------------
__device__ __forceinline__ uint32_t smem_u32(const void* p) {
    uint32_t a;
    asm("{ .reg .u64 t; cvta.to.shared.u64 t, %1; cvt.u32.u64 %0, t; }" : "=r"(a) : "l"(p));
    return a;
}
__device__ __forceinline__ void cpa16(uint32_t s, const void* g) {
    asm volatile("cp.async.cg.shared.global [%0], [%1], 16;" :: "r"(s), "l"(g));
}
__device__ __forceinline__ void cpa_commit() { asm volatile("cp.async.commit_group;" ::: "memory"); }
template <int N>
__device__ __forceinline__ void cpa_wait() { asm volatile("cp.async.wait_group %0;" :: "n"(N) : "memory"); }

__device__ __forceinline__ void ldsm_x4(uint32_t* r, uint32_t addr) {
    asm volatile("ldmatrix.sync.aligned.m8n8.x4.shared.b16 {%0,%1,%2,%3}, [%4];"
                 : "=r"(r[0]), "=r"(r[1]), "=r"(r[2]), "=r"(r[3]) : "r"(addr));
}
__device__ __forceinline__ void ldsm_x4_t(uint32_t* r, uint32_t addr) {
    asm volatile("ldmatrix.sync.aligned.m8n8.x4.trans.shared.b16 {%0,%1,%2,%3}, [%4];"
                 : "=r"(r[0]), "=r"(r[1]), "=r"(r[2]), "=r"(r[3]) : "r"(addr));
}
__device__ __forceinline__ void mma16816(float* d, const uint32_t* a, const uint32_t* b) {
    asm volatile(
        "mma.sync.aligned.m16n8k16.row.col.f32.f16.f16.f32 "
        "{%0,%1,%2,%3}, {%4,%5,%6,%7}, {%8,%9}, {%0,%1,%2,%3};"
        : "+f"(d[0]), "+f"(d[1]), "+f"(d[2]), "+f"(d[3])
        : "r"(a[0]), "r"(a[1]), "r"(a[2]), "r"(a[3]), "r"(b[0]), "r"(b[1]));
}

__device__ __forceinline__ float geluf(float x) {
    float inner = 0.7978845608028654f * (x + 0.044715f * x * x * x);
    return 0.5f * x * (1.f + tanhf(inner));
}

// ------- mma.sync fp16 GEMM: tile 128x128, 256 thr, warp tile 32x64 --------
// MODE 1: gelu(acc+bias) -> fp16 Ch
// MODE 3: fp32 partial -> Cf (+ optional split-K via blockIdx.y)
// MODE 4: QKV fused epilogue: bias + RMSNorm + RoPE + fp16
#define BK 64
#define PITCHB 144
#define A_MAT (128 * PITCHB)
#define B_MAT (128 * PITCHB)
#define STAGE_BYTES (A_MAT + B_MAT)       // 36864
#define NSTG 3
#define GEMM_SMEM (NSTG * STAGE_BYTES)    // 110592

__device__ __forceinline__ void load_mat(uint32_t dst, const __half* g, int ld,
                                         int row0, int k0, int tid) {
    const __half* gp = g + (size_t)row0 * ld + k0;
#pragma unroll
    for (int i = 0; i < 4; i++) {
        int idx = tid + i * 256;
        int row = idx >> 3;
        int c = idx & 7;
        cpa16(dst + row * PITCHB + c * 16, gp + (size_t)row * ld + c * 8);
    }
}

template <int MODE>
__global__ __launch_bounds__(256, 2)
void gemm_mma(const __half* __restrict__ Ah,
              const __half* __restrict__ Bh,
              int Mtot, int Ktot, int lda, int ldb,
              const float* __restrict__ bias,
              float* __restrict__ Cf, int ldc,
              __half* __restrict__ Ch, int ldch,
              const float* __restrict__ rc, const float* __restrict__ rs,
              const float* __restrict__ wqr, const float* __restrict__ wkr,
              __half* __restrict__ qh, __half* __restrict__ kh,
              __half* __restrict__ vh) {
    extern __shared__ char smem[];
    uint32_t sb = smem_u32(smem);
    int tid = threadIdx.x;
    int warp = tid >> 5, lane = tid & 31;
    int wm = warp & 3;
    int wn = warp >> 2;

    int kidx = blockIdx.y;
    const __half* A = Ah + (size_t)kidx * Ktot;
    const __half* B = Bh + (size_t)kidx * Ktot;
    float* Cpart = Cf + (size_t)kidx * ((size_t)S_LEN * DIM);

    int mtiles = Mtot >> 7;
    int bm0 = (blockIdx.x % mtiles) << 7;
    int bn0 = (blockIdx.x / mtiles) << 7;

    float acc[2][8][4];
#pragma unroll
    for (int i = 0; i < 2; i++)
#pragma unroll
        for (int j = 0; j < 8; j++)
#pragma unroll
            for (int c = 0; c < 4; c++) acc[i][j][c] = 0.f;

    const int iters = Ktot / BK;

#pragma unroll
    for (int s = 0; s < 2; s++) {
        uint32_t st = sb + s * STAGE_BYTES;
        load_mat(st, A, lda, bm0, s * BK, tid);
        load_mat(st + A_MAT, B, ldb, bn0, s * BK, tid);
        cpa_commit();
    }

    uint32_t a_off = (uint32_t)(wm * 32 + (lane & 15)) * PITCHB + ((lane >> 4) * 8) * 2;
    uint32_t b_off = (uint32_t)(wn * 64 + ((lane >> 4) & 1) * 8 + (lane & 7)) * PITCHB
                   + (((lane >> 3) & 1) * 8) * 2;

    for (int it = 0; it < iters; ++it) {
        int s = it % NSTG;
        if (it + 1 < iters) cpa_wait<1>(); else cpa_wait<0>();
        __syncthreads();

        if (it + 2 < iters) {
            int s2 = (it + 2) % NSTG;
            uint32_t st = sb + s2 * STAGE_BYTES;
            int k0 = (it + 2) * BK;
            load_mat(st, A, lda, bm0, k0, tid);
            load_mat(st + A_MAT, B, ldb, bn0, k0, tid);
            cpa_commit();
        }

        uint32_t stg = sb + s * STAGE_BYTES;
#pragma unroll
        for (int kk = 0; kk < 4; kk++) {
            uint32_t kb = kk * 32;
            uint32_t bbase = stg + A_MAT + b_off + kb;
            uint32_t bhbuf[2][4];
            ldsm_x4(bhbuf[0], bbase);                       // p = 0 early
            uint32_t ah[2][4];
#pragma unroll
            for (int mi = 0; mi < 2; mi++)
                ldsm_x4(ah[mi], stg + a_off + (uint32_t)mi * 16 * PITCHB + kb);
#pragma unroll
            for (int p = 0; p < 4; p++) {
                if (p < 3)
                    ldsm_x4(bhbuf[(p + 1) & 1], bbase + (uint32_t)(p + 1) * 16 * PITCHB);
                const uint32_t* bh = bhbuf[p & 1];
#pragma unroll
                for (int mi = 0; mi < 2; mi++) {
                    mma16816(acc[mi][2 * p + 0], ah[mi], bh + 0);
                    mma16816(acc[mi][2 * p + 1], ah[mi], bh + 2);
                }
            }
        }
    }

    int rq = lane >> 2;
    int cq = (lane & 3) * 2;

    if (MODE == 4) {
#pragma unroll
        for (int mi = 0; mi < 2; mi++)
#pragma unroll
            for (int ni = 0; ni < 8; ni++) {
                int n = bn0 + wn * 64 + ni * 8 + cq;
#pragma unroll
                for (int half = 0; half < 2; half++) {
                    acc[mi][ni][half * 2 + 0] += bias[n];
                    acc[mi][ni][half * 2 + 1] += bias[n + 1];
                }
            }
        int region = bn0 / DIM;          // 0=q 1=k 2=v
        int roff = region * DIM;
        if (region < 2) {
            float ssq[4];
#pragma unroll
            for (int r = 0; r < 4; r++) ssq[r] = 0.f;
#pragma unroll
            for (int mi = 0; mi < 2; mi++)
#pragma unroll
                for (int ni = 0; ni < 8; ni++)
#pragma unroll
                    for (int half = 0; half < 2; half++) {
                        float v0 = acc[mi][ni][half * 2 + 0];
                        float v1 = acc[mi][ni][half * 2 + 1];
                        ssq[mi * 2 + half] += v0 * v0 + v1 * v1;
                    }
#pragma unroll
            for (int r = 0; r < 4; r++) {
                ssq[r] += __shfl_xor_sync(0xffffffffu, ssq[r], 1);
                ssq[r] += __shfl_xor_sync(0xffffffffu, ssq[r], 2);
            }
            __syncthreads();
            float* red = (float*)smem;
            if ((lane & 3) == 0) {
#pragma unroll
                for (int mi = 0; mi < 2; mi++)
#pragma unroll
                    for (int half = 0; half < 2; half++) {
                        int rowl = wm * 32 + mi * 16 + rq + half * 8;
                        red[rowl * 2 + wn] = ssq[mi * 2 + half];
                    }
            }
            __syncthreads();
            const float qscale = 0.08838834764831845f;
#pragma unroll
            for (int mi = 0; mi < 2; mi++)
#pragma unroll
                for (int half = 0; half < 2; half++) {
                    int rowl = wm * 32 + mi * 16 + rq + half * 8;
                    size_t m = (size_t)bm0 + rowl;
                    float tot = red[rowl * 2 + 0] + red[rowl * 2 + 1];
                    float rstd = rsqrtf(tot * (1.f / HEAD_DIM) + 1e-6f);
#pragma unroll
                    for (int ni = 0; ni < 8; ni++) {
                        int n = bn0 + wn * 64 + ni * 8 + cq;
                        int d0 = n & (HEAD_DIM - 1);
                        float v0 = acc[mi][ni][half * 2 + 0];
                        float v1 = acc[mi][ni][half * 2 + 1];
                        float w0 = (region == 0) ? wqr[d0] : wkr[d0];
                        float w1 = (region == 0) ? wqr[d0 + 1] : wkr[d0 + 1];
                        float xn0 = v0 * rstd * w0;
                        float xn1 = v1 * rstd * w1;
                        float2 cs = *(const float2*)(rc + m * HEAD_DIM + d0);
                        float2 sn = *(const float2*)(rs + m * HEAD_DIM + d0);
                        float o0 = xn0 * cs.x - xn1 * sn.x;
                        float o1 = xn1 * cs.y + xn0 * sn.y;
                        size_t gout = m * DIM + (n - roff);
                        if (region == 0) {
                            *(__half2*)(qh + gout) =
                                __floats2half2_rn(o0 * qscale, o1 * qscale);
                        } else {
                            *(__half2*)(kh + gout) = __floats2half2_rn(o0, o1);
                        }
                    }
                }
        } else {
#pragma unroll
            for (int mi = 0; mi < 2; mi++)
#pragma unroll
                for (int ni = 0; ni < 8; ni++) {
                    int n = bn0 + wn * 64 + ni * 8 + cq;
#pragma unroll
                    for (int half = 0; half < 2; half++) {
                        size_t m = (size_t)bm0 + wm * 32 + mi * 16 + rq + half * 8;
                        *(__half2*)(vh + m * DIM + (n - roff)) =
                            __floats2half2_rn(acc[mi][ni][half * 2 + 0],
                                              acc[mi][ni][half * 2 + 1]);
                    }
                }
        }
        return;
    }

#pragma unroll
    for (int mi = 0; mi < 2; mi++) {
#pragma unroll
        for (int ni = 0; ni < 8; ni++) {
            int n = bn0 + wn * 64 + ni * 8 + cq;
#pragma unroll
            for (int half = 0; half < 2; half++) {
                size_t m = (size_t)bm0 + wm * 32 + mi * 16 + rq + half * 8;
                float v0 = acc[mi][ni][half * 2 + 0];
                float v1 = acc[mi][ni][half * 2 + 1];
                if (MODE == 1) {
                    float g0 = geluf(v0 + bias[n]);
                    float g1 = geluf(v1 + bias[n + 1]);
                    *(__half2*)(Ch + m * ldch + n) = __floats2half2_rn(g0, g1);
                } else {  // MODE 3
                    *(float2*)(Cpart + m * ldc + n) = make_float2(v0, v1);
                }
            }
        }
    }
}

// ---------------- weight conversions (vectorized, split) --------------------
#define QW_N ((long)DIM * DIM)
#define QKV_W_TOTAL (3 * QW_N)
#define REST_TOTAL ((long)MLP_H * DIM + (long)DIM * CAT_K)

__device__ __forceinline__ void cvt8(const float* src, __half* dst, long off) {
    float4 a = *(const float4*)(src + off);
    float4 b = *(const float4*)(src + off + 4);
    __half2 h[4];
    h[0] = __floats2half2_rn(a.x, a.y);
    h[1] = __floats2half2_rn(a.z, a.w);
    h[2] = __floats2half2_rn(b.x, b.y);
    h[3] = __floats2half2_rn(b.z, b.w);
    *(uint4*)(dst + off) = *(uint4*)h;
}

__global__ void cvt_qkv(const float* __restrict__ q_w, const float* __restrict__ k_w,
                        const float* __restrict__ v_w, __half* __restrict__ wqkv,
                        const float* __restrict__ q_b, const float* __restrict__ k_b,
                        const float* __restrict__ v_b, float* __restrict__ bqkv) {
    long t = (long)blockIdx.x * blockDim.x + threadIdx.x;
    if (t < 3 * DIM / 4) {
        int i = (int)t * 4;
        const float* src = i < DIM ? q_b : (i < 2 * DIM ? k_b : v_b);
        *(float4*)(bqkv + i) = *(const float4*)(src + (i % DIM));
    }
    long i = t * 8;
    if (i >= QKV_W_TOTAL) return;
    if (i < QW_N) cvt8(q_w, wqkv, i);
    else if (i < 2 * QW_N) cvt8(k_w - QW_N, wqkv, i);
    else cvt8(v_w - 2 * QW_N, wqkv, i);
}

__global__ void cvt_rest(const float* __restrict__ mlp_w, const float* __restrict__ out_w,
                         __half* __restrict__ wm, __half* __restrict__ wo) {
    long i = ((long)blockIdx.x * blockDim.x + threadIdx.x) * 8;
    if (i >= REST_TOTAL) return;
    if (i < (long)MLP_H * DIM) cvt8(mlp_w, wm, i);
    else cvt8(out_w, wo, i - (long)MLP_H * DIM);
}

// ---------------- partial reduce (3 partials) + gated residual --------------
__global__ void final_reduce(const float* __restrict__ p0, const float* __restrict__ p1,
                             const float* __restrict__ p2,
                             const float* __restrict__ hidden, const float* __restrict__ emb,
                             const float* __restrict__ ob, float* __restrict__ out) {
    size_t i = ((size_t)blockIdx.x * blockDim.x + threadIdx.x) * 4;
    if (i >= (size_t)S_LEN * DIM) return;
    int col = (int)(i % DIM);
    float4 a = *(const float4*)(p0 + i);
    float4 b = *(const float4*)(p1 + i);
    float4 c = *(const float4*)(p2 + i);
    float4 hv = *(const float4*)(hidden + i);
    float4 g = *(const float4*)(emb + 2 * DIM + col);
    float4 bb = *(const float4*)(ob + col);
    float4 o;
    o.x = hv.x + g.x * (a.x + b.x + c.x + bb.x);
    o.y = hv.y + g.y * (a.y + b.y + c.y + bb.y);
    o.z = hv.z + g.z * (a.z + b.z + c.z + bb.z);
    o.w = hv.w + g.w * (a.w + b.w + c.w + bb.w);
    *(float4*)(out + i) = o;
}

// ---------------- adaLN embedding GEMV with fused silu ----------------
__global__ __launch_bounds__(128) void emb_gemv(const float* __restrict__ temb,
                                                const float* __restrict__ w,
                                                const float* __restrict__ b,
                                                float* __restrict__ emb) {
    int jrow = blockIdx.x;
    const float* wr = w + (size_t)jrow * DIM;
    int tid = threadIdx.x;
    float s = 0.f;
    for (int i = tid * 4; i < DIM; i += 512) {
        float4 a = *(const float4*)(temb + i);
        float4 ww = *(const float4*)(wr + i);
        a.x = a.x / (1.f + __expf(-a.x));
        a.y = a.y / (1.f + __expf(-a.y));
        a.z = a.z / (1.f + __expf(-a.z));
        a.w = a.w / (1.f + __expf(-a.w));
        s += a.x * ww.x + a.y * ww.y + a.z * ww.z + a.w * ww.w;
    }
    for (int o = 16; o > 0; o >>= 1) s += __shfl_xor_sync(0xffffffffu, s, o);
    __shared__ float sm[4];
    if ((tid & 31) == 0) sm[tid >> 5] = s;
    __syncthreads();
    if (tid == 0) emb[jrow] = sm[0] + sm[1] + sm[2] + sm[3] + b[jrow];
}

// LayerNorm + adaLN modulate -> single fp16
__global__ __launch_bounds__(256) void ln_mod(const float* __restrict__ x,
                                              const float* __restrict__ emb,
                                              __half* __restrict__ nh) {
    int srow = blockIdx.x;
    int tid = threadIdx.x;
    const float* row = x + (size_t)srow * DIM;
    float sum = 0.f, sq = 0.f;
    for (int i = tid * 4; i < DIM; i += 1024) {
        float4 v = *(const float4*)(row + i);
        sum += v.x + v.y + v.z + v.w;
        sq += v.x * v.x + v.y * v.y + v.z * v.z + v.w * v.w;
    }
    for (int o = 16; o > 0; o >>= 1) {
        sum += __shfl_xor_sync(0xffffffffu, sum, o);
        sq += __shfl_xor_sync(0xffffffffu, sq, o);
    }
    __shared__ float s1[8], s2[8];
    if ((tid & 31) == 0) { s1[tid >> 5] = sum; s2[tid >> 5] = sq; }
    __syncthreads();
    sum = 0.f; sq = 0.f;
#pragma unroll
    for (int w = 0; w < 8; w++) { sum += s1[w]; sq += s2[w]; }
    float mean = sum * (1.f / DIM);
    float var = sq * (1.f / DIM) - mean * mean;
    float rstd = rsqrtf(var + 1e-6f);
    __half* oh = nh + (size_t)srow * DIM;
    for (int i = tid * 4; i < DIM; i += 1024) {
        float4 v = *(const float4*)(row + i);
        float4 sc = *(const float4*)(emb + DIM + i);
        float4 sh = *(const float4*)(emb + i);
        float o0 = (v.x - mean) * rstd * (1.f + sc.x) + sh.x;
        float o1 = (v.y - mean) * rstd * (1.f + sc.y) + sh.y;
        float o2 = (v.z - mean) * rstd * (1.f + sc.z) + sh.z;
        float o3 = (v.w - mean) * rstd * (1.f + sc.w) + sh.w;
        *(__half2*)(oh + i) = __floats2half2_rn(o0, o1);
        *(__half2*)(oh + i + 2) = __floats2half2_rn(o2, o3);
    }
}

// ---------------- HMMA flash attention (QK 1-pass, PV 1-pass) ---------------
#define AT_PITCH 272
#define QMAT (128 * AT_PITCH)
#define KVMAT (64 * AT_PITCH)
#define KVSTG (2 * KVMAT)                   // Kh, Vh
#define FLASH_SMEM (QMAT + 2 * KVSTG)       // 104448

__device__ __forceinline__ void load_kv_stage(uint32_t dst,
        const __half* Kh, const __half* Vh, int key0, int hd, int tid) {
#pragma unroll
    for (int i = 0; i < 8; i++) {
        int idx = tid + i * 256;
        int mat = idx >> 10;
        int rem = idx & 1023;
        int row = rem >> 4, c = rem & 15;
        const __half* src = (mat == 0) ? Kh : Vh;
        cpa16(dst + mat * KVMAT + row * AT_PITCH + c * 16,
              src + (size_t)(key0 + row) * DIM + hd * HEAD_DIM + c * 8);
    }
}

__global__ __launch_bounds__(256, 1) void flash_mma(
        const __half* __restrict__ Qh_,
        const __half* __restrict__ Kh_, const __half* __restrict__ Vh_,
        __half* __restrict__ Oh) {
    extern __shared__ char smem[];
    uint32_t sb = smem_u32(smem);
    const uint32_t qbase = sb;
    const uint32_t kvbase = sb + QMAT;
    int tid = threadIdx.x, warp = tid >> 5, lane = tid & 31;
    int hd = blockIdx.y;
    int q0 = blockIdx.x * 128;

#pragma unroll
    for (int i = 0; i < 8; i++) {
        int idx = tid + i * 256;
        int row = idx >> 4, c = idx & 15;
        cpa16(qbase + row * AT_PITCH + c * 16,
              Qh_ + (size_t)(q0 + row) * DIM + hd * HEAD_DIM + c * 8);
    }
    load_kv_stage(kvbase, Kh_, Vh_, 0, hd, tid);
    cpa_commit();
    load_kv_stage(kvbase + KVSTG, Kh_, Vh_, 64, hd, tid);
    cpa_commit();

    float out[16][4];
#pragma unroll
    for (int i = 0; i < 16; i++)
#pragma unroll
        for (int j = 0; j < 4; j++) out[i][j] = 0.f;
    float m0 = -1e30f, m1 = -1e30f, l0 = 0.f, l1 = 0.f;

    uint32_t a_off = (uint32_t)(warp * 16 + (lane & 15)) * AT_PITCH + ((lane >> 4) * 8) * 2;
    uint32_t kb_off = (uint32_t)(((lane >> 4) & 1) * 8 + (lane & 7)) * AT_PITCH
                    + (((lane >> 3) & 1) * 8) * 2;
    uint32_t v_off = (uint32_t)(((lane >> 3) & 1) * 8 + (lane & 7)) * AT_PITCH
                   + ((lane >> 4) * 8) * 2;

    const int iters = S_LEN / 64;
    for (int it = 0; it < iters; ++it) {
        int s = it & 1;
        if (it + 1 < iters) cpa_wait<1>(); else cpa_wait<0>();
        __syncthreads();

        uint32_t khb = kvbase + s * KVSTG;
        uint32_t vhb = khb + KVMAT;

        float C[8][4];
#pragma unroll
        for (int i = 0; i < 8; i++)
#pragma unroll
            for (int j = 0; j < 4; j++) C[i][j] = 0.f;

#pragma unroll
        for (int kt = 0; kt < 8; kt++) {
            uint32_t qa = qbase + a_off + kt * 32;
            uint32_t qv[4];
            ldsm_x4(qv, qa);
#pragma unroll
            for (int kb = 0; kb < 4; kb++) {
                uint32_t bh[4];
                uint32_t ka = khb + kb_off + (uint32_t)kb * 16 * AT_PITCH + kt * 32;
                ldsm_x4(bh, ka);
                mma16816(C[2 * kb], qv, bh);
                mma16816(C[2 * kb + 1], qv, bh + 2);
            }
        }

        float t0 = -1e30f, t1 = -1e30f;
#pragma unroll
        for (int nt = 0; nt < 8; nt++) {
            t0 = fmaxf(t0, fmaxf(C[nt][0], C[nt][1]));
            t1 = fmaxf(t1, fmaxf(C[nt][2], C[nt][3]));
        }
        t0 = fmaxf(t0, __shfl_xor_sync(0xffffffffu, t0, 1));
        t0 = fmaxf(t0, __shfl_xor_sync(0xffffffffu, t0, 2));
        t1 = fmaxf(t1, __shfl_xor_sync(0xffffffffu, t1, 1));
        t1 = fmaxf(t1, __shfl_xor_sync(0xffffffffu, t1, 2));
        float mn0 = fmaxf(m0, t0), mn1 = fmaxf(m1, t1);
        float c0 = __expf(m0 - mn0), c1 = __expf(m1 - mn1);
        m0 = mn0; m1 = mn1;
        l0 *= c0; l1 *= c1;
#pragma unroll
        for (int nt = 0; nt < 16; nt++) {
            out[nt][0] *= c0; out[nt][1] *= c0;
            out[nt][2] *= c1; out[nt][3] *= c1;
        }
#pragma unroll
        for (int nt = 0; nt < 8; nt++) {
            C[nt][0] = __expf(C[nt][0] - m0);
            C[nt][1] = __expf(C[nt][1] - m0);
            C[nt][2] = __expf(C[nt][2] - m1);
            C[nt][3] = __expf(C[nt][3] - m1);
            l0 += C[nt][0] + C[nt][1];
            l1 += C[nt][2] + C[nt][3];
        }

#pragma unroll
        for (int ks = 0; ks < 4; ks++) {
            uint32_t ph[4];
            {
                __half2 hh;
                hh = __floats2half2_rn(C[2 * ks][0], C[2 * ks][1]);
                ph[0] = *(uint32_t*)&hh;
                hh = __floats2half2_rn(C[2 * ks][2], C[2 * ks][3]);
                ph[1] = *(uint32_t*)&hh;
                hh = __floats2half2_rn(C[2 * ks + 1][0], C[2 * ks + 1][1]);
                ph[2] = *(uint32_t*)&hh;
                hh = __floats2half2_rn(C[2 * ks + 1][2], C[2 * ks + 1][3]);
                ph[3] = *(uint32_t*)&hh;
            }
#pragma unroll
            for (int dp = 0; dp < 8; dp++) {
                uint32_t vv[4];
                uint32_t va = vhb + v_off + (uint32_t)ks * 16 * AT_PITCH + dp * 32;
                ldsm_x4_t(vv, va);
                mma16816(out[2 * dp], ph, vv);
                mma16816(out[2 * dp + 1], ph, vv + 2);
            }
        }

        __syncthreads();
        if (it + 2 < iters) {
            load_kv_stage(kvbase + s * KVSTG, Kh_, Vh_, (it + 2) * 64, hd, tid);
            cpa_commit();
        }
    }

    l0 += __shfl_xor_sync(0xffffffffu, l0, 1);
    l0 += __shfl_xor_sync(0xffffffffu, l0, 2);
    l1 += __shfl_xor_sync(0xffffffffu, l1, 1);
    l1 += __shfl_xor_sync(0xffffffffu, l1, 2);
    float i0 = 1.f / l0, i1 = 1.f / l1;
    int r0 = q0 + warp * 16 + (lane >> 2);
    int r1 = r0 + 8;
    int cb = hd * HEAD_DIM + (lane & 3) * 2;
#pragma unroll
    for (int nt = 0; nt < 16; nt++) {
        int col = cb + nt * 8;
        *(__half2*)(Oh + (size_t)r0 * DIM + col) =
            __floats2half2_rn(out[nt][0] * i0, out[nt][1] * i0);
        *(__half2*)(Oh + (size_t)r1 * DIM + col) =
            __floats2half2_rn(out[nt][2] * i1, out[nt][3] * i1);
    }
}

// ---------------- launch (fork-join stream DAG, capture-safe) ----------------
static cudaStream_t g_s1 = nullptr, g_s2 = nullptr;
static cudaEvent_t g_eFork, g_eQW, g_eRW, g_eQKV, g_eP0;

extern "C" void kernel_launch(void* const* d_in, const int* in_sizes, int n_in,
                              void* d_out, int out_size) {
    const float* hidden = (const float*)d_in[0];
    const float* temb = (const float*)d_in[1];
    const float* rope_cos = (const float*)d_in[2];
    const float* rope_sin = (const float*)d_in[3];
    const float* norm_w = (const float*)d_in[4];
    const float* norm_b = (const float*)d_in[5];
    const float* mlp_w = (const float*)d_in[6];
    const float* mlp_b = (const float*)d_in[7];
    const float* q_w = (const float*)d_in[8];
    const float* q_b = (const float*)d_in[9];
    const float* k_w = (const float*)d_in[10];
    const float* k_b = (const float*)d_in[11];
    const float* v_w = (const float*)d_in[12];
    const float* v_b = (const float*)d_in[13];
    const float* rms_q_w = (const float*)d_in[14];
    const float* rms_k_w = (const float*)d_in[15];
    const float* out_w = (const float*)d_in[16];
    const float* out_b = (const float*)d_in[17];
    float* out = (float*)d_out;

    float *emb_p, *bqkv_p, *part_p;
    __half *nh, *wqkv, *wm, *wo, *mlpb, *attnh;
    __half *qh, *kh, *vh;
    cudaGetSymbolAddress((void**)&emb_p, g_emb);
    cudaGetSymbolAddress((void**)&bqkv_p, g_bqkv);
    cudaGetSymbolAddress((void**)&part_p, g_part);
    cudaGetSymbolAddress((void**)&nh, g_nh);
    cudaGetSymbolAddress((void**)&wqkv, g_wqkv);
    cudaGetSymbolAddress((void**)&wm, g_wm);
    cudaGetSymbolAddress((void**)&wo, g_wo);
    cudaGetSymbolAddress((void**)&mlpb, g_mlp);
    cudaGetSymbolAddress((void**)&attnh, g_attnh);
    cudaGetSymbolAddress((void**)&qh, g_qh);
    cudaGetSymbolAddress((void**)&kh, g_kh);
    cudaGetSymbolAddress((void**)&vh, g_vh);

    if (!g_s1) {
        cudaStreamCreateWithFlags(&g_s1, cudaStreamNonBlocking);
        cudaStreamCreateWithFlags(&g_s2, cudaStreamNonBlocking);
        cudaEventCreateWithFlags(&g_eFork, cudaEventDisableTiming);
        cudaEventCreateWithFlags(&g_eQW, cudaEventDisableTiming);
        cudaEventCreateWithFlags(&g_eRW, cudaEventDisableTiming);
        cudaEventCreateWithFlags(&g_eQKV, cudaEventDisableTiming);
        cudaEventCreateWithFlags(&g_eP0, cudaEventDisableTiming);
        cudaFuncSetAttribute(gemm_mma<1>, cudaFuncAttributeMaxDynamicSharedMemorySize, GEMM_SMEM);
        cudaFuncSetAttribute(gemm_mma<3>, cudaFuncAttributeMaxDynamicSharedMemorySize, GEMM_SMEM);
        cudaFuncSetAttribute(gemm_mma<4>, cudaFuncAttributeMaxDynamicSharedMemorySize, GEMM_SMEM);
        cudaFuncSetAttribute(flash_mma, cudaFuncAttributeMaxDynamicSharedMemorySize, FLASH_SMEM);
    }
    cudaStream_t s0 = (cudaStream_t)0;

    // fork: qkv weight conversion on s1 (issued first)
    cudaEventRecord(g_eFork, s0);
    cudaStreamWaitEvent(g_s1, g_eFork, 0);
    cvt_qkv<<<(unsigned)((QKV_W_TOTAL / 8 + 255) / 256), 256, 0, g_s1>>>(
        q_w, k_w, v_w, wqkv, q_b, k_b, v_b, bqkv_p);
    cudaEventRecord(g_eQW, g_s1);

    // main: emb + ln  (launches #2, #3)
    emb_gemv<<<3 * DIM, 128, 0, s0>>>(temb, norm_w, norm_b, emb_p);
    ln_mod<<<S_LEN, 256, 0, s0>>>(hidden, emb_p, nh);

    // launch #4: QKV GEMM with fused rmsnorm+rope epilogue (ncu profiles this)
    cudaStreamWaitEvent(s0, g_eQW, 0);
    gemm_mma<4><<<dim3((S_LEN / 128) * (QKV_N / 128), 1), 256, GEMM_SMEM, s0>>>(
        nh, wqkv, S_LEN, DIM, DIM, DIM,
        bqkv_p, nullptr, 0, nullptr, 0,
        rope_cos, rope_sin, rms_q_w, rms_k_w, qh, kh, vh);
    cudaEventRecord(g_eQKV, s0);

    // remaining weight conversion on s1 (issued after QKV; runs concurrently)
    cvt_rest<<<(unsigned)((REST_TOTAL / 8 + 255) / 256), 256, 0, g_s1>>>(
        mlp_w, out_w, wm, wo);
    cudaEventRecord(g_eRW, g_s1);

    // fork: attention chain + out-proj attn-part on s2
    cudaStreamWaitEvent(g_s2, g_eQKV, 0);
    flash_mma<<<dim3(S_LEN / 128, HEADS), 256, FLASH_SMEM, g_s2>>>(qh, kh, vh, attnh);
    cudaStreamWaitEvent(g_s2, g_eRW, 0);
    gemm_mma<3><<<dim3((S_LEN / 128) * (DIM / 128), 1), 256, GEMM_SMEM, g_s2>>>(
        attnh, wo, S_LEN, DIM, DIM, CAT_K,
        nullptr, part_p, DIM, nullptr, 0,
        nullptr, nullptr, nullptr, nullptr, nullptr, nullptr, nullptr);
    cudaEventRecord(g_eP0, g_s2);

    // main: MLP GEMM, then out-proj mlp-part (split-K=2 over K=12288)
    cudaStreamWaitEvent(s0, g_eRW, 0);
    gemm_mma<1><<<dim3((S_LEN / 128) * (MLP_H / 128), 1), 256, GEMM_SMEM, s0>>>(
        nh, wm, S_LEN, DIM, DIM, DIM,
        mlp_b, nullptr, 0, mlpb, MLP_H,
        nullptr, nullptr, nullptr, nullptr, nullptr, nullptr, nullptr);
    gemm_mma<3><<<dim3((S_LEN / 128) * (DIM / 128), 2), 256, GEMM_SMEM, s0>>>(
        mlpb, wo + DIM, S_LEN, MLP_H / 2, MLP_H, CAT_K,
        nullptr, part_p + (size_t)S_LEN * DIM, DIM, nullptr, 0,
        nullptr, nullptr, nullptr, nullptr, nullptr, nullptr, nullptr);

    // join; final reduce + gated residual
    cudaStreamWaitEvent(s0, g_eP0, 0);
    final_reduce<<<(S_LEN * DIM / 4 + 255) / 256, 256, 0, s0>>>(
        part_p, part_p + (size_t)S_LEN * DIM, part_p + 2 * (size_t)S_LEN * DIM,
        hidden, emb_p, out_b, out);
}

// round 16
// speedup vs baseline: 1.0097x; 1.0097x over previous
#include <cuda_runtime.h>
#include <cuda_fp16.h>
#include <cstdint>
#include <math.h>

#define S_LEN 2048
#define DIM 3072
#define HEADS 24
#define HEAD_DIM 128
#define MLP_H 12288
#define CAT_K (DIM + MLP_H)   // 15360
#define QKV_N (3 * DIM)       // 9216

// ---------------- scratch (device globals; no runtime allocs allowed) -------
#define ALN __align__(128)
__device__ ALN float g_emb[3 * DIM];
__device__ ALN float g_bqkv[QKV_N];
__device__ ALN float g_part[3 * S_LEN * DIM];
__device__ ALN __half g_nh[S_LEN * DIM];
__device__ ALN __half g_wqkv[QKV_N * DIM];
__device__ ALN __half g_wm[MLP_H * DIM];
__device__ ALN __half g_wo[DIM * CAT_K];
__device__ ALN __half g_mlp[S_LEN * MLP_H];
__device__ ALN __half g_attnh[S_LEN * DIM];
__device__ ALN __half g_qh[S_LEN * DIM];
__device__ ALN __half g_kh[S_LEN * DIM];
__device__ ALN __half g_vh[S_LEN * DIM];

// ---------------- PTX helpers ----------------
__device__ __forceinline__ uint32_t smem_u32(const void* p) {
    uint32_t a;
    asm("{ .reg .u64 t; cvta.to.shared.u64 t, %1; cvt.u32.u64 %0, t; }" : "=r"(a) : "l"(p));
    return a;
}
__device__ __forceinline__ void cpa16(uint32_t s, const void* g) {
    asm volatile("cp.async.cg.shared.global [%0], [%1], 16;" :: "r"(s), "l"(g));
}
__device__ __forceinline__ void cpa_commit() { asm volatile("cp.async.commit_group;" ::: "memory"); }
template <int N>
__device__ __forceinline__ void cpa_wait() { asm volatile("cp.async.wait_group %0;" :: "n"(N) : "memory"); }

__device__ __forceinline__ void ldsm_x4(uint32_t* r, uint32_t addr) {
    asm volatile("ldmatrix.sync.aligned.m8n8.x4.shared.b16 {%0,%1,%2,%3}, [%4];"
                 : "=r"(r[0]), "=r"(r[1]), "=r"(r[2]), "=r"(r[3]) : "r"(addr));
}
__device__ __forceinline__ void ldsm_x4_t(uint32_t* r, uint32_t addr) {
    asm volatile("ldmatrix.sync.aligned.m8n8.x4.trans.shared.b16 {%0,%1,%2,%3}, [%4];"
                 : "=r"(r[0]), "=r"(r[1]), "=r"(r[2]), "=r"(r[3]) : "r"(addr));
}
__device__ __forceinline__ void mma16816(float* d, const uint32_t* a, const uint32_t* b) {
    asm volatile(
        "mma.sync.aligned.m16n8k16.row.col.f32.f16.f16.f32 "
        "{%0,%1,%2,%3}, {%4,%5,%6,%7}, {%8,%9}, {%0,%1,%2,%3};"
        : "+f"(d[0]), "+f"(d[1]), "+f"(d[2]), "+f"(d[3])
        : "r"(a[0]), "r"(a[1]), "r"(a[2]), "r"(a[3]), "r"(b[0]), "r"(b[1]));
}

__device__ __forceinline__ float geluf(float x) {
    float inner = 0.7978845608028654f * (x + 0.044715f * x * x * x);
    return 0.5f * x * (1.f + tanhf(inner));
}

// ------- mma.sync fp16 GEMM: tile 128x128, 256 thr, warp tile 32x64 --------
// MODE 1: gelu(acc+bias) -> fp16 Ch
// MODE 3: fp32 partial -> Cf (+ optional split-K via blockIdx.y)
// MODE 4: QKV fused epilogue: bias + RMSNorm + RoPE + fp16
#define BK 64
#define PITCHB 144
#define A_MAT (128 * PITCHB)
#define B_MAT (128 * PITCHB)
#define STAGE_BYTES (A_MAT + B_MAT)       // 36864
#define NSTG 3
#define GEMM_SMEM (NSTG * STAGE_BYTES)    // 110592

__device__ __forceinline__ void load_mat(uint32_t dst, const __half* g, int ld,
                                         int row0, int k0, int tid) {
    const __half* gp = g + (size_t)row0 * ld + k0;
#pragma unroll
    for (int i = 0; i < 4; i++) {
        int idx = tid + i * 256;
        int row = idx >> 3;
        int c = idx & 7;
        cpa16(dst + row * PITCHB + c * 16, gp + (size_t)row * ld + c * 8);
    }
}

template <int MODE>
__global__ __launch_bounds__(256, 2)
void gemm_mma(const __half* __restrict__ Ah,
              const __half* __restrict__ Bh,
              int Mtot, int Ktot, int lda, int ldb,
              const float* __restrict__ bias,
              float* __restrict__ Cf, int ldc,
              __half* __restrict__ Ch, int ldch,
              const float* __restrict__ rc, const float* __restrict__ rs,
              const float* __restrict__ wqr, const float* __restrict__ wkr,
              __half* __restrict__ qh, __half* __restrict__ kh,
              __half* __restrict__ vh) {
    extern __shared__ char smem[];
    uint32_t sb = smem_u32(smem);
    int tid = threadIdx.x;
    int warp = tid >> 5, lane = tid & 31;
    int wm = warp & 3;
    int wn = warp >> 2;

    int kidx = blockIdx.y;
    const __half* A = Ah + (size_t)kidx * Ktot;
    const __half* B = Bh + (size_t)kidx * Ktot;
    float* Cpart = Cf + (size_t)kidx * ((size_t)S_LEN * DIM);

    int mtiles = Mtot >> 7;
    int bm0 = (blockIdx.x % mtiles) << 7;
    int bn0 = (blockIdx.x / mtiles) << 7;

    float acc[2][8][4];
#pragma unroll
    for (int i = 0; i < 2; i++)
#pragma unroll
        for (int j = 0; j < 8; j++)
#pragma unroll
            for (int c = 0; c < 4; c++) acc[i][j][c] = 0.f;

    const int iters = Ktot / BK;

#pragma unroll
    for (int s = 0; s < 2; s++) {
        uint32_t st = sb + s * STAGE_BYTES;
        load_mat(st, A, lda, bm0, s * BK, tid);
        load_mat(st + A_MAT, B, ldb, bn0, s * BK, tid);
        cpa_commit();
    }

    uint32_t a_off = (uint32_t)(wm * 32 + (lane & 15)) * PITCHB + ((lane >> 4) * 8) * 2;
    uint32_t b_off = (uint32_t)(wn * 64 + ((lane >> 4) & 1) * 8 + (lane & 7)) * PITCHB
                   + (((lane >> 3) & 1) * 8) * 2;

    for (int it = 0; it < iters; ++it) {
        int s = it % NSTG;
        if (it + 1 < iters) cpa_wait<1>(); else cpa_wait<0>();
        __syncthreads();

        if (it + 2 < iters) {
            int s2 = (it + 2) % NSTG;
            uint32_t st = sb + s2 * STAGE_BYTES;
            int k0 = (it + 2) * BK;
            load_mat(st, A, lda, bm0, k0, tid);
            load_mat(st + A_MAT, B, ldb, bn0, k0, tid);
            cpa_commit();
        }

        uint32_t stg = sb + s * STAGE_BYTES;
#pragma unroll
        for (int kk = 0; kk < 4; kk++) {
            uint32_t kb = kk * 32;
            uint32_t ah[2][4];
#pragma unroll
            for (int mi = 0; mi < 2; mi++)
                ldsm_x4(ah[mi], stg + a_off + (uint32_t)mi * 16 * PITCHB + kb);
#pragma unroll
            for (int p = 0; p < 4; p++) {
                uint32_t bh[4];
                ldsm_x4(bh, stg + A_MAT + b_off + (uint32_t)p * 16 * PITCHB + kb);
#pragma unroll
                for (int mi = 0; mi < 2; mi++) {
                    mma16816(acc[mi][2 * p + 0], ah[mi], bh + 0);
                    mma16816(acc[mi][2 * p + 1], ah[mi], bh + 2);
                }
            }
        }
    }

    int rq = lane >> 2;
    int cq = (lane & 3) * 2;

    if (MODE == 4) {
#pragma unroll
        for (int mi = 0; mi < 2; mi++)
#pragma unroll
            for (int ni = 0; ni < 8; ni++) {
                int n = bn0 + wn * 64 + ni * 8 + cq;
#pragma unroll
                for (int half = 0; half < 2; half++) {
                    acc[mi][ni][half * 2 + 0] += bias[n];
                    acc[mi][ni][half * 2 + 1] += bias[n + 1];
                }
            }
        int region = bn0 / DIM;          // 0=q 1=k 2=v
        int roff = region * DIM;
        if (region < 2) {
            float ssq[4];
#pragma unroll
            for (int r = 0; r < 4; r++) ssq[r] = 0.f;
#pragma unroll
            for (int mi = 0; mi < 2; mi++)
#pragma unroll
                for (int ni = 0; ni < 8; ni++)
#pragma unroll
                    for (int half = 0; half < 2; half++) {
                        float v0 = acc[mi][ni][half * 2 + 0];
                        float v1 = acc[mi][ni][half * 2 + 1];
                        ssq[mi * 2 + half] += v0 * v0 + v1 * v1;
                    }
#pragma unroll
            for (int r = 0; r < 4; r++) {
                ssq[r] += __shfl_xor_sync(0xffffffffu, ssq[r], 1);
                ssq[r] += __shfl_xor_sync(0xffffffffu, ssq[r], 2);
            }
            __syncthreads();
            float* red = (float*)smem;
            if ((lane & 3) == 0) {
#pragma unroll
                for (int mi = 0; mi < 2; mi++)
#pragma unroll
                    for (int half = 0; half < 2; half++) {
                        int rowl = wm * 32 + mi * 16 + rq + half * 8;
                        red[rowl * 2 + wn] = ssq[mi * 2 + half];
                    }
            }
            __syncthreads();
            const float qscale = 0.08838834764831845f;
#pragma unroll
            for (int mi = 0; mi < 2; mi++)
#pragma unroll
                for (int half = 0; half < 2; half++) {
                    int rowl = wm * 32 + mi * 16 + rq + half * 8;
                    size_t m = (size_t)bm0 + rowl;
                    float tot = red[rowl * 2 + 0] + red[rowl * 2 + 1];
                    float rstd = rsqrtf(tot * (1.f / HEAD_DIM) + 1e-6f);
#pragma unroll
                    for (int ni = 0; ni < 8; ni++) {
                        int n = bn0 + wn * 64 + ni * 8 + cq;
                        int d0 = n & (HEAD_DIM - 1);
                        float v0 = acc[mi][ni][half * 2 + 0];
                        float v1 = acc[mi][ni][half * 2 + 1];
                        float w0 = (region == 0) ? wqr[d0] : wkr[d0];
                        float w1 = (region == 0) ? wqr[d0 + 1] : wkr[d0 + 1];
                        float xn0 = v0 * rstd * w0;
                        float xn1 = v1 * rstd * w1;
                        float2 cs = *(const float2*)(rc + m * HEAD_DIM + d0);
                        float2 sn = *(const float2*)(rs + m * HEAD_DIM + d0);
                        float o0 = xn0 * cs.x - xn1 * sn.x;
                        float o1 = xn1 * cs.y + xn0 * sn.y;
                        size_t gout = m * DIM + (n - roff);
                        if (region == 0) {
                            *(__half2*)(qh + gout) =
                                __floats2half2_rn(o0 * qscale, o1 * qscale);
                        } else {
                            *(__half2*)(kh + gout) = __floats2half2_rn(o0, o1);
                        }
                    }
                }
        } else {
#pragma unroll
            for (int mi = 0; mi < 2; mi++)
#pragma unroll
                for (int ni = 0; ni < 8; ni++) {
                    int n = bn0 + wn * 64 + ni * 8 + cq;
#pragma unroll
                    for (int half = 0; half < 2; half++) {
                        size_t m = (size_t)bm0 + wm * 32 + mi * 16 + rq + half * 8;
                        *(__half2*)(vh + m * DIM + (n - roff)) =
                            __floats2half2_rn(acc[mi][ni][half * 2 + 0],
                                              acc[mi][ni][half * 2 + 1]);
                    }
                }
        }
        return;
    }

#pragma unroll
    for (int mi = 0; mi < 2; mi++) {
#pragma unroll
        for (int ni = 0; ni < 8; ni++) {
            int n = bn0 + wn * 64 + ni * 8 + cq;
#pragma unroll
            for (int half = 0; half < 2; half++) {
                size_t m = (size_t)bm0 + wm * 32 + mi * 16 + rq + half * 8;
                float v0 = acc[mi][ni][half * 2 + 0];
                float v1 = acc[mi][ni][half * 2 + 1];
                if (MODE == 1) {
                    float g0 = geluf(v0 + bias[n]);
                    float g1 = geluf(v1 + bias[n + 1]);
                    *(__half2*)(Ch + m * ldch + n) = __floats2half2_rn(g0, g1);
                } else {  // MODE 3
                    *(float2*)(Cpart + m * ldc + n) = make_float2(v0, v1);
                }
            }
        }
    }
}

// ---------------- weight conversions (vectorized, split) --------------------
#define QW_N ((long)DIM * DIM)
#define QKV_W_TOTAL (3 * QW_N)
#define REST_TOTAL ((long)MLP_H * DIM + (long)DIM * CAT_K)

__device__ __forceinline__ void cvt8(const float* src, __half* dst, long off) {
    float4 a = *(const float4*)(src + off);
    float4 b = *(const float4*)(src + off + 4);
    __half2 h[4];
    h[0] = __floats2half2_rn(a.x, a.y);
    h[1] = __floats2half2_rn(a.z, a.w);
    h[2] = __floats2half2_rn(b.x, b.y);
    h[3] = __floats2half2_rn(b.z, b.w);
    *(uint4*)(dst + off) = *(uint4*)h;
}

__global__ void cvt_qkv(const float* __restrict__ q_w, const float* __restrict__ k_w,
                        const float* __restrict__ v_w, __half* __restrict__ wqkv,
                        const float* __restrict__ q_b, const float* __restrict__ k_b,
                        const float* __restrict__ v_b, float* __restrict__ bqkv) {
    long t = (long)blockIdx.x * blockDim.x + threadIdx.x;
    if (t < 3 * DIM / 4) {
        int i = (int)t * 4;
        const float* src = i < DIM ? q_b : (i < 2 * DIM ? k_b : v_b);
        *(float4*)(bqkv + i) = *(const float4*)(src + (i % DIM));
    }
    long i = t * 8;
    if (i >= QKV_W_TOTAL) return;
    if (i < QW_N) cvt8(q_w, wqkv, i);
    else if (i < 2 * QW_N) cvt8(k_w - QW_N, wqkv, i);
    else cvt8(v_w - 2 * QW_N, wqkv, i);
}

__global__ void cvt_rest(const float* __restrict__ mlp_w, const float* __restrict__ out_w,
                         __half* __restrict__ wm, __half* __restrict__ wo) {
    long i = ((long)blockIdx.x * blockDim.x + threadIdx.x) * 8;
    if (i >= REST_TOTAL) return;
    if (i < (long)MLP_H * DIM) cvt8(mlp_w, wm, i);
    else cvt8(out_w, wo, i - (long)MLP_H * DIM);
}

// ---------------- partial reduce (3 partials) + gated residual --------------
__global__ void final_reduce(const float* __restrict__ p0, const float* __restrict__ p1,
                             const float* __restrict__ p2,
                             const float* __restrict__ hidden, const float* __restrict__ emb,
                             const float* __restrict__ ob, float* __restrict__ out) {
    size_t i = ((size_t)blockIdx.x * blockDim.x + threadIdx.x) * 4;
    if (i >= (size_t)S_LEN * DIM) return;
    int col = (int)(i % DIM);
    float4 a = *(const float4*)(p0 + i);
    float4 b = *(const float4*)(p1 + i);
    float4 c = *(const float4*)(p2 + i);
    float4 hv = *(const float4*)(hidden + i);
    float4 g = *(const float4*)(emb + 2 * DIM + col);
    float4 bb = *(const float4*)(ob + col);
    float4 o;
    o.x = hv.x + g.x * (a.x + b.x + c.x + bb.x);
    o.y = hv.y + g.y * (a.y + b.y + c.y + bb.y);
    o.z = hv.z + g.z * (a.z + b.z + c.z + bb.z);
    o.w = hv.w + g.w * (a.w + b.w + c.w + bb.w);
    *(float4*)(out + i) = o;
}

// ---------------- adaLN embedding GEMV with fused silu ----------------
__global__ __launch_bounds__(128) void emb_gemv(const float* __restrict__ temb,
                                                const float* __restrict__ w,
                                                const float* __restrict__ b,
                                                float* __restrict__ emb) {
    int jrow = blockIdx.x;
    const float* wr = w + (size_t)jrow * DIM;
    int tid = threadIdx.x;
    float s = 0.f;
    for (int i = tid * 4; i < DIM; i += 512) {
        float4 a = *(const float4*)(temb + i);
        float4 ww = *(const float4*)(wr + i);
        a.x = a.x / (1.f + __expf(-a.x));
        a.y = a.y / (1.f + __expf(-a.y));
        a.z = a.z / (1.f + __expf(-a.z));
        a.w = a.w / (1.f + __expf(-a.w));
        s += a.x * ww.x + a.y * ww.y + a.z * ww.z + a.w * ww.w;
    }
    for (int o = 16; o > 0; o >>= 1) s += __shfl_xor_sync(0xffffffffu, s, o);
    __shared__ float sm[4];
    if ((tid & 31) == 0) sm[tid >> 5] = s;
    __syncthreads();
    if (tid == 0) emb[jrow] = sm[0] + sm[1] + sm[2] + sm[3] + b[jrow];
}

// LayerNorm + adaLN modulate -> single fp16
__global__ __launch_bounds__(256) void ln_mod(const float* __restrict__ x,
                                              const float* __restrict__ emb,
                                              __half* __restrict__ nh) {
    int srow = blockIdx.x;
    int tid = threadIdx.x;
    const float* row = x + (size_t)srow * DIM;
    float sum = 0.f, sq = 0.f;
    for (int i = tid * 4; i < DIM; i += 1024) {
        float4 v = *(const float4*)(row + i);
        sum += v.x + v.y + v.z + v.w;
        sq += v.x * v.x + v.y * v.y + v.z * v.z + v.w * v.w;
    }
    for (int o = 16; o > 0; o >>= 1) {
        sum += __shfl_xor_sync(0xffffffffu, sum, o);
        sq += __shfl_xor_sync(0xffffffffu, sq, o);
    }
    __shared__ float s1[8], s2[8];
    if ((tid & 31) == 0) { s1[tid >> 5] = sum; s2[tid >> 5] = sq; }
    __syncthreads();
    sum = 0.f; sq = 0.f;
#pragma unroll
    for (int w = 0; w < 8; w++) { sum += s1[w]; sq += s2[w]; }
    float mean = sum * (1.f / DIM);
    float var = sq * (1.f / DIM) - mean * mean;
    float rstd = rsqrtf(var + 1e-6f);
    __half* oh = nh + (size_t)srow * DIM;
    for (int i = tid * 4; i < DIM; i += 1024) {
        float4 v = *(const float4*)(row + i);
        float4 sc = *(const float4*)(emb + DIM + i);
        float4 sh = *(const float4*)(emb + i);
        float o0 = (v.x - mean) * rstd * (1.f + sc.x) + sh.x;
        float o1 = (v.y - mean) * rstd * (1.f + sc.y) + sh.y;
        float o2 = (v.z - mean) * rstd * (1.f + sc.z) + sh.z;
        float o3 = (v.w - mean) * rstd * (1.f + sc.w) + sh.w;
        *(__half2*)(oh + i) = __floats2half2_rn(o0, o1);
        *(__half2*)(oh + i + 2) = __floats2half2_rn(o2, o3);
    }
}

// ---------------- HMMA flash attention (QK 1-pass, PV 1-pass, 2 CTAs/SM) ----
#define AT_PITCH 272
#define QMAT (128 * AT_PITCH)
#define KVMAT (64 * AT_PITCH)
#define KVSTG (2 * KVMAT)                   // Kh, Vh
#define FLASH_SMEM (QMAT + 2 * KVSTG)       // 104448 -> 2 CTAs/SM

__device__ __forceinline__ void load_kv_stage(uint32_t dst,
        const __half* Kh, const __half* Vh, int key0, int hd, int tid) {
#pragma unroll
    for (int i = 0; i < 8; i++) {
        int idx = tid + i * 256;
        int mat = idx >> 10;
        int rem = idx & 1023;
        int row = rem >> 4, c = rem & 15;
        const __half* src = (mat == 0) ? Kh : Vh;
        cpa16(dst + mat * KVMAT + row * AT_PITCH + c * 16,
              src + (size_t)(key0 + row) * DIM + hd * HEAD_DIM + c * 8);
    }
}

__global__ __launch_bounds__(256, 2) void flash_mma(
        const __half* __restrict__ Qh_,
        const __half* __restrict__ Kh_, const __half* __restrict__ Vh_,
        __half* __restrict__ Oh) {
    extern __shared__ char smem[];
    uint32_t sb = smem_u32(smem);
    const uint32_t qbase = sb;
    const uint32_t kvbase = sb + QMAT;
    int tid = threadIdx.x, warp = tid >> 5, lane = tid & 31;
    int hd = blockIdx.y;
    int q0 = blockIdx.x * 128;

#pragma unroll
    for (int i = 0; i < 8; i++) {
        int idx = tid + i * 256;
        int row = idx >> 4, c = idx & 15;
        cpa16(qbase + row * AT_PITCH + c * 16,
              Qh_ + (size_t)(q0 + row) * DIM + hd * HEAD_DIM + c * 8);
    }
    load_kv_stage(kvbase, Kh_, Vh_, 0, hd, tid);
    cpa_commit();
    load_kv_stage(kvbase + KVSTG, Kh_, Vh_, 64, hd, tid);
    cpa_commit();

    float out[16][4];
#pragma unroll
    for (int i = 0; i < 16; i++)
#pragma unroll
        for (int j = 0; j < 4; j++) out[i][j] = 0.f;
    float m0 = -1e30f, m1 = -1e30f, l0 = 0.f, l1 = 0.f;

    uint32_t a_off = (uint32_t)(warp * 16 + (lane & 15)) * AT_PITCH + ((lane >> 4) * 8) * 2;
    uint32_t kb_off = (uint32_t)(((lane >> 4) & 1) * 8 + (lane & 7)) * AT_PITCH
                    + (((lane >> 3) & 1) * 8) * 2;
    uint32_t v_off = (uint32_t)(((lane >> 3) & 1) * 8 + (lane & 7)) * AT_PITCH
                   + ((lane >> 4) * 8) * 2;

    const int iters = S_LEN / 64;
    for (int it = 0; it < iters; ++it) {
        int s = it & 1;
        if (it + 1 < iters) cpa_wait<1>(); else cpa_wait<0>();
        __syncthreads();

        uint32_t khb = kvbase + s * KVSTG;
        uint32_t vhb = khb + KVMAT;

        float C[8][4];
#pragma unroll
        for (int i = 0; i < 8; i++)
#pragma unroll
            for (int j = 0; j < 4; j++) C[i][j] = 0.f;

#pragma unroll
        for (int kt = 0; kt < 8; kt++) {
            uint32_t qa = qbase + a_off + kt * 32;
            uint32_t qv[4];
            ldsm_x4(qv, qa);
#pragma unroll
            for (int kb = 0; kb < 4; kb++) {
                uint32_t bh[4];
                uint32_t ka = khb + kb_off + (uint32_t)kb * 16 * AT_PITCH + kt * 32;
                ldsm_x4(bh, ka);
                mma16816(C[2 * kb], qv, bh);
                mma16816(C[2 * kb + 1], qv, bh + 2);
            }
        }

        float t0 = -1e30f, t1 = -1e30f;
#pragma unroll
        for (int nt = 0; nt < 8; nt++) {
            t0 = fmaxf(t0, fmaxf(C[nt][0], C[nt][1]));
            t1 = fmaxf(t1, fmaxf(C[nt][2], C[nt][3]));
        }
        t0 = fmaxf(t0, __shfl_xor_sync(0xffffffffu, t0, 1));
        t0 = fmaxf(t0, __shfl_xor_sync(0xffffffffu, t0, 2));
        t1 = fmaxf(t1, __shfl_xor_sync(0xffffffffu, t1, 1));
        t1 = fmaxf(t1, __shfl_xor_sync(0xffffffffu, t1, 2));
        float mn0 = fmaxf(m0, t0), mn1 = fmaxf(m1, t1);
        float c0 = __expf(m0 - mn0), c1 = __expf(m1 - mn1);
        m0 = mn0; m1 = mn1;
        l0 *= c0; l1 *= c1;
#pragma unroll
        for (int nt = 0; nt < 16; nt++) {
            out[nt][0] *= c0; out[nt][1] *= c0;
            out[nt][2] *= c1; out[nt][3] *= c1;
        }
#pragma unroll
        for (int nt = 0; nt < 8; nt++) {
            C[nt][0] = __expf(C[nt][0] - m0);
            C[nt][1] = __expf(C[nt][1] - m0);
            C[nt][2] = __expf(C[nt][2] - m1);
            C[nt][3] = __expf(C[nt][3] - m1);
            l0 += C[nt][0] + C[nt][1];
            l1 += C[nt][2] + C[nt][3];
        }

#pragma unroll
        for (int ks = 0; ks < 4; ks++) {
            uint32_t ph[4];
            {
                __half2 hh;
                hh = __floats2half2_rn(C[2 * ks][0], C[2 * ks][1]);
                ph[0] = *(uint32_t*)&hh;
                hh = __floats2half2_rn(C[2 * ks][2], C[2 * ks][3]);
                ph[1] = *(uint32_t*)&hh;
                hh = __floats2half2_rn(C[2 * ks + 1][0], C[2 * ks + 1][1]);
                ph[2] = *(uint32_t*)&hh;
                hh = __floats2half2_rn(C[2 * ks + 1][2], C[2 * ks + 1][3]);
                ph[3] = *(uint32_t*)&hh;
            }
#pragma unroll
            for (int dp = 0; dp < 8; dp++) {
                uint32_t vv[4];
                uint32_t va = vhb + v_off + (uint32_t)ks * 16 * AT_PITCH + dp * 32;
                ldsm_x4_t(vv, va);
                mma16816(out[2 * dp], ph, vv);
                mma16816(out[2 * dp + 1], ph, vv + 2);
            }
        }

        __syncthreads();
        if (it + 2 < iters) {
            load_kv_stage(kvbase + s * KVSTG, Kh_, Vh_, (it + 2) * 64, hd, tid);
            cpa_commit();
        }
    }

    l0 += __shfl_xor_sync(0xffffffffu, l0, 1);
    l0 += __shfl_xor_sync(0xffffffffu, l0, 2);
    l1 += __shfl_xor_sync(0xffffffffu, l1, 1);
    l1 += __shfl_xor_sync(0xffffffffu, l1, 2);
    float i0 = 1.f / l0, i1 = 1.f / l1;
    int r0 = q0 + warp * 16 + (lane >> 2);
    int r1 = r0 + 8;
    int cb = hd * HEAD_DIM + (lane & 3) * 2;
#pragma unroll
    for (int nt = 0; nt < 16; nt++) {
        int col = cb + nt * 8;
        *(__half2*)(Oh + (size_t)r0 * DIM + col) =
            __floats2half2_rn(out[nt][0] * i0, out[nt][1] * i0);
        *(__half2*)(Oh + (size_t)r1 * DIM + col) =
            __floats2half2_rn(out[nt][2] * i1, out[nt][3] * i1);
    }
}

// ---------------- launch (fork-join stream DAG, capture-safe) ----------------
static cudaStream_t g_s1 = nullptr, g_s2 = nullptr;
static cudaEvent_t g_eFork, g_eQW, g_eRW, g_eQKV, g_eP0;

extern "C" void kernel_launch(void* const* d_in, const int* in_sizes, int n_in,
                              void* d_out, int out_size) {
    const float* hidden = (const float*)d_in[0];
    const float* temb = (const float*)d_in[1];
    const float* rope_cos = (const float*)d_in[2];
    const float* rope_sin = (const float*)d_in[3];
    const float* norm_w = (const float*)d_in[4];
    const float* norm_b = (const float*)d_in[5];
    const float* mlp_w = (const float*)d_in[6];
    const float* mlp_b = (const float*)d_in[7];
    const float* q_w = (const float*)d_in[8];
    const float* q_b = (const float*)d_in[9];
    const float* k_w = (const float*)d_in[10];
    const float* k_b = (const float*)d_in[11];
    const float* v_w = (const float*)d_in[12];
    const float* v_b = (const float*)d_in[13];
    const float* rms_q_w = (const float*)d_in[14];
    const float* rms_k_w = (const float*)d_in[15];
    const float* out_w = (const float*)d_in[16];
    const float* out_b = (const float*)d_in[17];
    float* out = (float*)d_out;

    float *emb_p, *bqkv_p, *part_p;
    __half *nh, *wqkv, *wm, *wo, *mlpb, *attnh;
    __half *qh, *kh, *vh;
    cudaGetSymbolAddress((void**)&emb_p, g_emb);
    cudaGetSymbolAddress((void**)&bqkv_p, g_bqkv);
    cudaGetSymbolAddress((void**)&part_p, g_part);
    cudaGetSymbolAddress((void**)&nh, g_nh);
    cudaGetSymbolAddress((void**)&wqkv, g_wqkv);
    cudaGetSymbolAddress((void**)&wm, g_wm);
    cudaGetSymbolAddress((void**)&wo, g_wo);
    cudaGetSymbolAddress((void**)&mlpb, g_mlp);
    cudaGetSymbolAddress((void**)&attnh, g_attnh);
    cudaGetSymbolAddress((void**)&qh, g_qh);
    cudaGetSymbolAddress((void**)&kh, g_kh);
    cudaGetSymbolAddress((void**)&vh, g_vh);

    if (!g_s1) {
        cudaStreamCreateWithFlags(&g_s1, cudaStreamNonBlocking);
        cudaStreamCreateWithFlags(&g_s2, cudaStreamNonBlocking);
        cudaEventCreateWithFlags(&g_eFork, cudaEventDisableTiming);
        cudaEventCreateWithFlags(&g_eQW, cudaEventDisableTiming);
        cudaEventCreateWithFlags(&g_eRW, cudaEventDisableTiming);
        cudaEventCreateWithFlags(&g_eQKV, cudaEventDisableTiming);
        cudaEventCreateWithFlags(&g_eP0, cudaEventDisableTiming);
        cudaFuncSetAttribute(gemm_mma<1>, cudaFuncAttributeMaxDynamicSharedMemorySize, GEMM_SMEM);
        cudaFuncSetAttribute(gemm_mma<3>, cudaFuncAttributeMaxDynamicSharedMemorySize, GEMM_SMEM);
        cudaFuncSetAttribute(gemm_mma<4>, cudaFuncAttributeMaxDynamicSharedMemorySize, GEMM_SMEM);
        cudaFuncSetAttribute(flash_mma, cudaFuncAttributeMaxDynamicSharedMemorySize, FLASH_SMEM);
    }
    cudaStream_t s0 = (cudaStream_t)0;

    // fork: qkv weight conversion on s1 (issued first)
    cudaEventRecord(g_eFork, s0);
    cudaStreamWaitEvent(g_s1, g_eFork, 0);
    cvt_qkv<<<(unsigned)((QKV_W_TOTAL / 8 + 255) / 256), 256, 0, g_s1>>>(
        q_w, k_w, v_w, wqkv, q_b, k_b, v_b, bqkv_p);
    cudaEventRecord(g_eQW, g_s1);

    // main: emb + ln
    emb_gemv<<<3 * DIM, 128, 0, s0>>>(temb, norm_w, norm_b, emb_p);
    ln_mod<<<S_LEN, 256, 0, s0>>>(hidden, emb_p, nh);

    // launch #4: QKV GEMM with fused rmsnorm+rope epilogue (ncu profiles this)
    cudaStreamWaitEvent(s0, g_eQW, 0);
    gemm_mma<4><<<dim3((S_LEN / 128) * (QKV_N / 128), 1), 256, GEMM_SMEM, s0>>>(
        nh, wqkv, S_LEN, DIM, DIM, DIM,
        bqkv_p, nullptr, 0, nullptr, 0,
        rope_cos, rope_sin, rms_q_w, rms_k_w, qh, kh, vh);
    cudaEventRecord(g_eQKV, s0);

    // remaining weight conversion on s1 (runs concurrently with QKV)
    cvt_rest<<<(unsigned)((REST_TOTAL / 8 + 255) / 256), 256, 0, g_s1>>>(
        mlp_w, out_w, wm, wo);
    cudaEventRecord(g_eRW, g_s1);

    // fork: attention chain + out-proj attn-part on s2
    cudaStreamWaitEvent(g_s2, g_eQKV, 0);
    flash_mma<<<dim3(S_LEN / 128, HEADS), 256, FLASH_SMEM, g_s2>>>(qh, kh, vh, attnh);
    cudaStreamWaitEvent(g_s2, g_eRW, 0);
    gemm_mma<3><<<dim3((S_LEN / 128) * (DIM / 128), 1), 256, GEMM_SMEM, g_s2>>>(
        attnh, wo, S_LEN, DIM, DIM, CAT_K,
        nullptr, part_p, DIM, nullptr, 0,
        nullptr, nullptr, nullptr, nullptr, nullptr, nullptr, nullptr);
    cudaEventRecord(g_eP0, g_s2);

    // main: MLP GEMM, then out-proj mlp-part (split-K=2 over K=12288)
    cudaStreamWaitEvent(s0, g_eRW, 0);
    gemm_mma<1><<<dim3((S_LEN / 128) * (MLP_H / 128), 1), 256, GEMM_SMEM, s0>>>(
        nh, wm, S_LEN, DIM, DIM, DIM,
        mlp_b, nullptr, 0, mlpb, MLP_H,
        nullptr, nullptr, nullptr, nullptr, nullptr, nullptr, nullptr);
    gemm_mma<3><<<dim3((S_LEN / 128) * (DIM / 128), 2), 256, GEMM_SMEM, s0>>>(
        mlpb, wo + DIM, S_LEN, MLP_H / 2, MLP_H, CAT_K,
        nullptr, part_p + (size_t)S_LEN * DIM, DIM, nullptr, 0,
        nullptr, nullptr, nullptr, nullptr, nullptr, nullptr, nullptr);

    // join; final reduce + gated residual
    cudaStreamWaitEvent(s0, g_eP0, 0);
    final_reduce<<<(S_LEN * DIM / 4 + 255) / 256, 256, 0, s0>>>(
        part_p, part_p + (size_t)S_LEN * DIM, part_p + 2 * (size_t)S_LEN * DIM,
        hidden, emb_p, out_b, out);
}

// round 17
// speedup vs baseline: 1.0271x; 1.0172x over previous
#include <cuda_runtime.h>
#include <cuda_fp16.h>
#include <cstdint>
#include <math.h>

#define S_LEN 2048
#define DIM 3072
#define HEADS 24
#define HEAD_DIM 128
#define MLP_H 12288
#define CAT_K (DIM + MLP_H)   // 15360
#define QKV_N (3 * DIM)       // 9216

// ---------------- scratch (device globals; no runtime allocs allowed) -------
#define ALN __align__(128)
__device__ ALN float g_emb[3 * DIM];
__device__ ALN float g_bqkv[QKV_N];
__device__ ALN float g_part[4 * S_LEN * DIM];
__device__ ALN __half g_nh[S_LEN * DIM];
__device__ ALN __half g_wqkv[QKV_N * DIM];
__device__ ALN __half g_wm[MLP_H * DIM];
__device__ ALN __half g_wo[DIM * CAT_K];
__device__ ALN __half g_mlp[S_LEN * MLP_H];
__device__ ALN __half g_attnh[S_LEN * DIM];
__device__ ALN __half g_qh[S_LEN * DIM];
__device__ ALN __half g_kh[S_LEN * DIM];
__device__ ALN __half g_vh[S_LEN * DIM];

// ---------------- PTX helpers ----------------
__device__ __forceinline__ uint32_t smem_u32(const void* p) {
    uint32_t a;
    asm("{ .reg .u64 t; cvta.to.shared.u64 t, %1; cvt.u32.u64 %0, t; }" : "=r"(a) : "l"(p));
    return a;
}
__device__ __forceinline__ void cpa16(uint32_t s, const void* g) {
    asm volatile("cp.async.cg.shared.global [%0], [%1], 16;" :: "r"(s), "l"(g));
}
__device__ __forceinline__ void cpa_commit() { asm volatile("cp.async.commit_group;" ::: "memory"); }
template <int N>
__device__ __forceinline__ void cpa_wait() { asm volatile("cp.async.wait_group %0;" :: "n"(N) : "memory"); }

__device__ __forceinline__ void ldsm_x4(uint32_t* r, uint32_t addr) {
    asm volatile("ldmatrix.sync.aligned.m8n8.x4.shared.b16 {%0,%1,%2,%3}, [%4];"
                 : "=r"(r[0]), "=r"(r[1]), "=r"(r[2]), "=r"(r[3]) : "r"(addr));
}
__device__ __forceinline__ void ldsm_x4_t(uint32_t* r, uint32_t addr) {
    asm volatile("ldmatrix.sync.aligned.m8n8.x4.trans.shared.b16 {%0,%1,%2,%3}, [%4];"
                 : "=r"(r[0]), "=r"(r[1]), "=r"(r[2]), "=r"(r[3]) : "r"(addr));
}
__device__ __forceinline__ void mma16816(float* d, const uint32_t* a, const uint32_t* b) {
    asm volatile(
        "mma.sync.aligned.m16n8k16.row.col.f32.f16.f16.f32 "
        "{%0,%1,%2,%3}, {%4,%5,%6,%7}, {%8,%9}, {%0,%1,%2,%3};"
        : "+f"(d[0]), "+f"(d[1]), "+f"(d[2]), "+f"(d[3])
        : "r"(a[0]), "r"(a[1]), "r"(a[2]), "r"(a[3]), "r"(b[0]), "r"(b[1]));
}

__device__ __forceinline__ float geluf(float x) {
    float inner = 0.7978845608028654f * (x + 0.044715f * x * x * x);
    return 0.5f * x * (1.f + tanhf(inner));
}

// ------- mma.sync fp16 GEMM: tile 128x128, 256 thr, warp tile 32x64 --------
// MODE 1: gelu(acc+bias) -> fp16 Ch
// MODE 3: fp32 partial -> Cf (+ optional split-K via blockIdx.y)
// MODE 4: QKV fused epilogue: bias + RMSNorm + RoPE + fp16
#define BK 64
#define PITCHB 144
#define A_MAT (128 * PITCHB)
#define B_MAT (128 * PITCHB)
#define STAGE_BYTES (A_MAT + B_MAT)       // 36864
#define NSTG 3
#define GEMM_SMEM (NSTG * STAGE_BYTES)    // 110592

__device__ __forceinline__ void load_mat(uint32_t dst, const __half* g, int ld,
                                         int row0, int k0, int tid) {
    const __half* gp = g + (size_t)row0 * ld + k0;
#pragma unroll
    for (int i = 0; i < 4; i++) {
        int idx = tid + i * 256;
        int row = idx >> 3;
        int c = idx & 7;
        cpa16(dst + row * PITCHB + c * 16, gp + (size_t)row * ld + c * 8);
    }
}

template <int MODE>
__global__ __launch_bounds__(256, 2)
void gemm_mma(const __half* __restrict__ Ah,
              const __half* __restrict__ Bh,
              int Mtot, int Ktot, int lda, int ldb,
              const float* __restrict__ bias,
              float* __restrict__ Cf, int ldc,
              __half* __restrict__ Ch, int ldch,
              const float* __restrict__ rc, const float* __restrict__ rs,
              const float* __restrict__ wqr, const float* __restrict__ wkr,
              __half* __restrict__ qh, __half* __restrict__ kh,
              __half* __restrict__ vh) {
    extern __shared__ char smem[];
    uint32_t sb = smem_u32(smem);
    int tid = threadIdx.x;
    int warp = tid >> 5, lane = tid & 31;
    int wm = warp & 3;
    int wn = warp >> 2;

    int kidx = blockIdx.y;
    const __half* A = Ah + (size_t)kidx * Ktot;
    const __half* B = Bh + (size_t)kidx * Ktot;
    float* Cpart = Cf + (size_t)kidx * ((size_t)S_LEN * DIM);

    int mtiles = Mtot >> 7;
    int bm0 = (blockIdx.x % mtiles) << 7;
    int bn0 = (blockIdx.x / mtiles) << 7;

    float acc[2][8][4];
#pragma unroll
    for (int i = 0; i < 2; i++)
#pragma unroll
        for (int j = 0; j < 8; j++)
#pragma unroll
            for (int c = 0; c < 4; c++) acc[i][j][c] = 0.f;

    const int iters = Ktot / BK;

#pragma unroll
    for (int s = 0; s < 2; s++) {
        uint32_t st = sb + s * STAGE_BYTES;
        load_mat(st, A, lda, bm0, s * BK, tid);
        load_mat(st + A_MAT, B, ldb, bn0, s * BK, tid);
        cpa_commit();
    }

    uint32_t a_off = (uint32_t)(wm * 32 + (lane & 15)) * PITCHB + ((lane >> 4) * 8) * 2;
    uint32_t b_off = (uint32_t)(wn * 64 + ((lane >> 4) & 1) * 8 + (lane & 7)) * PITCHB
                   + (((lane >> 3) & 1) * 8) * 2;

    for (int it = 0; it < iters; ++it) {
        int s = it % NSTG;
        if (it + 1 < iters) cpa_wait<1>(); else cpa_wait<0>();
        __syncthreads();

        if (it + 2 < iters) {
            int s2 = (it + 2) % NSTG;
            uint32_t st = sb + s2 * STAGE_BYTES;
            int k0 = (it + 2) * BK;
            load_mat(st, A, lda, bm0, k0, tid);
            load_mat(st + A_MAT, B, ldb, bn0, k0, tid);
            cpa_commit();
        }

        uint32_t stg = sb + s * STAGE_BYTES;
#pragma unroll
        for (int kk = 0; kk < 4; kk++) {
            uint32_t kb = kk * 32;
            uint32_t ah[2][4];
#pragma unroll
            for (int mi = 0; mi < 2; mi++)
                ldsm_x4(ah[mi], stg + a_off + (uint32_t)mi * 16 * PITCHB + kb);
#pragma unroll
            for (int p = 0; p < 4; p++) {
                uint32_t bh[4];
                ldsm_x4(bh, stg + A_MAT + b_off + (uint32_t)p * 16 * PITCHB + kb);
#pragma unroll
                for (int mi = 0; mi < 2; mi++) {
                    mma16816(acc[mi][2 * p + 0], ah[mi], bh + 0);
                    mma16816(acc[mi][2 * p + 1], ah[mi], bh + 2);
                }
            }
        }
    }

    int rq = lane >> 2;
    int cq = (lane & 3) * 2;

    if (MODE == 4) {
#pragma unroll
        for (int mi = 0; mi < 2; mi++)
#pragma unroll
            for (int ni = 0; ni < 8; ni++) {
                int n = bn0 + wn * 64 + ni * 8 + cq;
#pragma unroll
                for (int half = 0; half < 2; half++) {
                    acc[mi][ni][half * 2 + 0] += bias[n];
                    acc[mi][ni][half * 2 + 1] += bias[n + 1];
                }
            }
        int region = bn0 / DIM;          // 0=q 1=k 2=v
        int roff = region * DIM;
        if (region < 2) {
            float ssq[4];
#pragma unroll
            for (int r = 0; r < 4; r++) ssq[r] = 0.f;
#pragma unroll
            for (int mi = 0; mi < 2; mi++)
#pragma unroll
                for (int ni = 0; ni < 8; ni++)
#pragma unroll
                    for (int half = 0; half < 2; half++) {
                        float v0 = acc[mi][ni][half * 2 + 0];
                        float v1 = acc[mi][ni][half * 2 + 1];
                        ssq[mi * 2 + half] += v0 * v0 + v1 * v1;
                    }
#pragma unroll
            for (int r = 0; r < 4; r++) {
                ssq[r] += __shfl_xor_sync(0xffffffffu, ssq[r], 1);
                ssq[r] += __shfl_xor_sync(0xffffffffu, ssq[r], 2);
            }
            __syncthreads();
            float* red = (float*)smem;
            if ((lane & 3) == 0) {
#pragma unroll
                for (int mi = 0; mi < 2; mi++)
#pragma unroll
                    for (int half = 0; half < 2; half++) {
                        int rowl = wm * 32 + mi * 16 + rq + half * 8;
                        red[rowl * 2 + wn] = ssq[mi * 2 + half];
                    }
            }
            __syncthreads();
            const float qscale = 0.08838834764831845f;
#pragma unroll
            for (int mi = 0; mi < 2; mi++)
#pragma unroll
                for (int half = 0; half < 2; half++) {
                    int rowl = wm * 32 + mi * 16 + rq + half * 8;
                    size_t m = (size_t)bm0 + rowl;
                    float tot = red[rowl * 2 + 0] + red[rowl * 2 + 1];
                    float rstd = rsqrtf(tot * (1.f / HEAD_DIM) + 1e-6f);
#pragma unroll
                    for (int ni = 0; ni < 8; ni++) {
                        int n = bn0 + wn * 64 + ni * 8 + cq;
                        int d0 = n & (HEAD_DIM - 1);
                        float v0 = acc[mi][ni][half * 2 + 0];
                        float v1 = acc[mi][ni][half * 2 + 1];
                        float w0 = (region == 0) ? wqr[d0] : wkr[d0];
                        float w1 = (region == 0) ? wqr[d0 + 1] : wkr[d0 + 1];
                        float xn0 = v0 * rstd * w0;
                        float xn1 = v1 * rstd * w1;
                        float2 cs = *(const float2*)(rc + m * HEAD_DIM + d0);
                        float2 sn = *(const float2*)(rs + m * HEAD_DIM + d0);
                        float o0 = xn0 * cs.x - xn1 * sn.x;
                        float o1 = xn1 * cs.y + xn0 * sn.y;
                        size_t gout = m * DIM + (n - roff);
                        if (region == 0) {
                            *(__half2*)(qh + gout) =
                                __floats2half2_rn(o0 * qscale, o1 * qscale);
                        } else {
                            *(__half2*)(kh + gout) = __floats2half2_rn(o0, o1);
                        }
                    }
                }
        } else {
#pragma unroll
            for (int mi = 0; mi < 2; mi++)
#pragma unroll
                for (int ni = 0; ni < 8; ni++) {
                    int n = bn0 + wn * 64 + ni * 8 + cq;
#pragma unroll
                    for (int half = 0; half < 2; half++) {
                        size_t m = (size_t)bm0 + wm * 32 + mi * 16 + rq + half * 8;
                        *(__half2*)(vh + m * DIM + (n - roff)) =
                            __floats2half2_rn(acc[mi][ni][half * 2 + 0],
                                              acc[mi][ni][half * 2 + 1]);
                    }
                }
        }
        return;
    }

#pragma unroll
    for (int mi = 0; mi < 2; mi++) {
#pragma unroll
        for (int ni = 0; ni < 8; ni++) {
            int n = bn0 + wn * 64 + ni * 8 + cq;
#pragma unroll
            for (int half = 0; half < 2; half++) {
                size_t m = (size_t)bm0 + wm * 32 + mi * 16 + rq + half * 8;
                float v0 = acc[mi][ni][half * 2 + 0];
                float v1 = acc[mi][ni][half * 2 + 1];
                if (MODE == 1) {
                    float g0 = geluf(v0 + bias[n]);
                    float g1 = geluf(v1 + bias[n + 1]);
                    *(__half2*)(Ch + m * ldch + n) = __floats2half2_rn(g0, g1);
                } else {  // MODE 3
                    *(float2*)(Cpart + m * ldc + n) = make_float2(v0, v1);
                }
            }
        }
    }
}

// ---------------- weight conversions (vectorized, split) --------------------
#define QW_N ((long)DIM * DIM)
#define QKV_W_TOTAL (3 * QW_N)
#define REST_TOTAL ((long)MLP_H * DIM + (long)DIM * CAT_K)

__device__ __forceinline__ void cvt8(const float* src, __half* dst, long off) {
    float4 a = *(const float4*)(src + off);
    float4 b = *(const float4*)(src + off + 4);
    __half2 h[4];
    h[0] = __floats2half2_rn(a.x, a.y);
    h[1] = __floats2half2_rn(a.z, a.w);
    h[2] = __floats2half2_rn(b.x, b.y);
    h[3] = __floats2half2_rn(b.z, b.w);
    *(uint4*)(dst + off) = *(uint4*)h;
}

__global__ void cvt_qkv(const float* __restrict__ q_w, const float* __restrict__ k_w,
                        const float* __restrict__ v_w, __half* __restrict__ wqkv,
                        const float* __restrict__ q_b, const float* __restrict__ k_b,
                        const float* __restrict__ v_b, float* __restrict__ bqkv) {
    long t = (long)blockIdx.x * blockDim.x + threadIdx.x;
    if (t < 3 * DIM / 4) {
        int i = (int)t * 4;
        const float* src = i < DIM ? q_b : (i < 2 * DIM ? k_b : v_b);
        *(float4*)(bqkv + i) = *(const float4*)(src + (i % DIM));
    }
    long i = t * 8;
    if (i >= QKV_W_TOTAL) return;
    if (i < QW_N) cvt8(q_w, wqkv, i);
    else if (i < 2 * QW_N) cvt8(k_w - QW_N, wqkv, i);
    else cvt8(v_w - 2 * QW_N, wqkv, i);
}

__global__ void cvt_rest(const float* __restrict__ mlp_w, const float* __restrict__ out_w,
                         __half* __restrict__ wm, __half* __restrict__ wo) {
    long i = ((long)blockIdx.x * blockDim.x + threadIdx.x) * 8;
    if (i >= REST_TOTAL) return;
    if (i < (long)MLP_H * DIM) cvt8(mlp_w, wm, i);
    else cvt8(out_w, wo, i - (long)MLP_H * DIM);
}

// ---------------- partial reduce (4 partials) + gated residual --------------
__global__ void final_reduce(const float* __restrict__ p0, const float* __restrict__ p1,
                             const float* __restrict__ p2, const float* __restrict__ p3,
                             const float* __restrict__ hidden, const float* __restrict__ emb,
                             const float* __restrict__ ob, float* __restrict__ out) {
    size_t i = ((size_t)blockIdx.x * blockDim.x + threadIdx.x) * 4;
    if (i >= (size_t)S_LEN * DIM) return;
    int col = (int)(i % DIM);
    float4 a = *(const float4*)(p0 + i);
    float4 b = *(const float4*)(p1 + i);
    float4 c = *(const float4*)(p2 + i);
    float4 d = *(const float4*)(p3 + i);
    float4 hv = *(const float4*)(hidden + i);
    float4 g = *(const float4*)(emb + 2 * DIM + col);
    float4 bb = *(const float4*)(ob + col);
    float4 o;
    o.x = hv.x + g.x * (a.x + b.x + c.x + d.x + bb.x);
    o.y = hv.y + g.y * (a.y + b.y + c.y + d.y + bb.y);
    o.z = hv.z + g.z * (a.z + b.z + c.z + d.z + bb.z);
    o.w = hv.w + g.w * (a.w + b.w + c.w + d.w + bb.w);
    *(float4*)(out + i) = o;
}

// ---------------- adaLN embedding GEMV with fused silu ----------------
__global__ __launch_bounds__(128) void emb_gemv(const float* __restrict__ temb,
                                                const float* __restrict__ w,
                                                const float* __restrict__ b,
                                                float* __restrict__ emb) {
    int jrow = blockIdx.x;
    const float* wr = w + (size_t)jrow * DIM;
    int tid = threadIdx.x;
    float s = 0.f;
    for (int i = tid * 4; i < DIM; i += 512) {
        float4 a = *(const float4*)(temb + i);
        float4 ww = *(const float4*)(wr + i);
        a.x = a.x / (1.f + __expf(-a.x));
        a.y = a.y / (1.f + __expf(-a.y));
        a.z = a.z / (1.f + __expf(-a.z));
        a.w = a.w / (1.f + __expf(-a.w));
        s += a.x * ww.x + a.y * ww.y + a.z * ww.z + a.w * ww.w;
    }
    for (int o = 16; o > 0; o >>= 1) s += __shfl_xor_sync(0xffffffffu, s, o);
    __shared__ float sm[4];
    if ((tid & 31) == 0) sm[tid >> 5] = s;
    __syncthreads();
    if (tid == 0) emb[jrow] = sm[0] + sm[1] + sm[2] + sm[3] + b[jrow];
}

// LayerNorm + adaLN modulate -> single fp16
__global__ __launch_bounds__(256) void ln_mod(const float* __restrict__ x,
                                              const float* __restrict__ emb,
                                              __half* __restrict__ nh) {
    int srow = blockIdx.x;
    int tid = threadIdx.x;
    const float* row = x + (size_t)srow * DIM;
    float sum = 0.f, sq = 0.f;
    for (int i = tid * 4; i < DIM; i += 1024) {
        float4 v = *(const float4*)(row + i);
        sum += v.x + v.y + v.z + v.w;
        sq += v.x * v.x + v.y * v.y + v.z * v.z + v.w * v.w;
    }
    for (int o = 16; o > 0; o >>= 1) {
        sum += __shfl_xor_sync(0xffffffffu, sum, o);
        sq += __shfl_xor_sync(0xffffffffu, sq, o);
    }
    __shared__ float s1[8], s2[8];
    if ((tid & 31) == 0) { s1[tid >> 5] = sum; s2[tid >> 5] = sq; }
    __syncthreads();
    sum = 0.f; sq = 0.f;
#pragma unroll
    for (int w = 0; w < 8; w++) { sum += s1[w]; sq += s2[w]; }
    float mean = sum * (1.f / DIM);
    float var = sq * (1.f / DIM) - mean * mean;
    float rstd = rsqrtf(var + 1e-6f);
    __half* oh = nh + (size_t)srow * DIM;
    for (int i = tid * 4; i < DIM; i += 1024) {
        float4 v = *(const float4*)(row + i);
        float4 sc = *(const float4*)(emb + DIM + i);
        float4 sh = *(const float4*)(emb + i);
        float o0 = (v.x - mean) * rstd * (1.f + sc.x) + sh.x;
        float o1 = (v.y - mean) * rstd * (1.f + sc.y) + sh.y;
        float o2 = (v.z - mean) * rstd * (1.f + sc.z) + sh.z;
        float o3 = (v.w - mean) * rstd * (1.f + sc.w) + sh.w;
        *(__half2*)(oh + i) = __floats2half2_rn(o0, o1);
        *(__half2*)(oh + i + 2) = __floats2half2_rn(o2, o3);
    }
}

// ---------------- HMMA flash attention (QK 1-pass, PV 1-pass, 2 CTAs/SM) ----
#define AT_PITCH 272
#define QMAT (128 * AT_PITCH)
#define KVMAT (64 * AT_PITCH)
#define KVSTG (2 * KVMAT)                   // Kh, Vh
#define FLASH_SMEM (QMAT + 2 * KVSTG)       // 104448 -> 2 CTAs/SM

__device__ __forceinline__ void load_kv_stage(uint32_t dst,
        const __half* Kh, const __half* Vh, int key0, int hd, int tid) {
#pragma unroll
    for (int i = 0; i < 8; i++) {
        int idx = tid + i * 256;
        int mat = idx >> 10;
        int rem = idx & 1023;
        int row = rem >> 4, c = rem & 15;
        const __half* src = (mat == 0) ? Kh : Vh;
        cpa16(dst + mat * KVMAT + row * AT_PITCH + c * 16,
              src + (size_t)(key0 + row) * DIM + hd * HEAD_DIM + c * 8);
    }
}

__global__ __launch_bounds__(256, 2) void flash_mma(
        const __half* __restrict__ Qh_,
        const __half* __restrict__ Kh_, const __half* __restrict__ Vh_,
        __half* __restrict__ Oh) {
    extern __shared__ char smem[];
    uint32_t sb = smem_u32(smem);
    const uint32_t qbase = sb;
    const uint32_t kvbase = sb + QMAT;
    int tid = threadIdx.x, warp = tid >> 5, lane = tid & 31;
    int hd = blockIdx.y;
    int q0 = blockIdx.x * 128;

#pragma unroll
    for (int i = 0; i < 8; i++) {
        int idx = tid + i * 256;
        int row = idx >> 4, c = idx & 15;
        cpa16(qbase + row * AT_PITCH + c * 16,
              Qh_ + (size_t)(q0 + row) * DIM + hd * HEAD_DIM + c * 8);
    }
    load_kv_stage(kvbase, Kh_, Vh_, 0, hd, tid);
    cpa_commit();
    load_kv_stage(kvbase + KVSTG, Kh_, Vh_, 64, hd, tid);
    cpa_commit();

    float out[16][4];
#pragma unroll
    for (int i = 0; i < 16; i++)
#pragma unroll
        for (int j = 0; j < 4; j++) out[i][j] = 0.f;
    float m0 = -1e30f, m1 = -1e30f, l0 = 0.f, l1 = 0.f;

    uint32_t a_off = (uint32_t)(warp * 16 + (lane & 15)) * AT_PITCH + ((lane >> 4) * 8) * 2;
    uint32_t kb_off = (uint32_t)(((lane >> 4) & 1) * 8 + (lane & 7)) * AT_PITCH
                    + (((lane >> 3) & 1) * 8) * 2;
    uint32_t v_off = (uint32_t)(((lane >> 3) & 1) * 8 + (lane & 7)) * AT_PITCH
                   + ((lane >> 4) * 8) * 2;

    const int iters = S_LEN / 64;
    for (int it = 0; it < iters; ++it) {
        int s = it & 1;
        if (it + 1 < iters) cpa_wait<1>(); else cpa_wait<0>();
        __syncthreads();

        uint32_t khb = kvbase + s * KVSTG;
        uint32_t vhb = khb + KVMAT;

        float C[8][4];
#pragma unroll
        for (int i = 0; i < 8; i++)
#pragma unroll
            for (int j = 0; j < 4; j++) C[i][j] = 0.f;

#pragma unroll
        for (int kt = 0; kt < 8; kt++) {
            uint32_t qa = qbase + a_off + kt * 32;
            uint32_t qv[4];
            ldsm_x4(qv, qa);
#pragma unroll
            for (int kb = 0; kb < 4; kb++) {
                uint32_t bh[4];
                uint32_t ka = khb + kb_off + (uint32_t)kb * 16 * AT_PITCH + kt * 32;
                ldsm_x4(bh, ka);
                mma16816(C[2 * kb], qv, bh);
                mma16816(C[2 * kb + 1], qv, bh + 2);
            }
        }

        float t0 = -1e30f, t1 = -1e30f;
#pragma unroll
        for (int nt = 0; nt < 8; nt++) {
            t0 = fmaxf(t0, fmaxf(C[nt][0], C[nt][1]));
            t1 = fmaxf(t1, fmaxf(C[nt][2], C[nt][3]));
        }
        t0 = fmaxf(t0, __shfl_xor_sync(0xffffffffu, t0, 1));
        t0 = fmaxf(t0, __shfl_xor_sync(0xffffffffu, t0, 2));
        t1 = fmaxf(t1, __shfl_xor_sync(0xffffffffu, t1, 1));
        t1 = fmaxf(t1, __shfl_xor_sync(0xffffffffu, t1, 2));
        float mn0 = fmaxf(m0, t0), mn1 = fmaxf(m1, t1);
        float c0 = __expf(m0 - mn0), c1 = __expf(m1 - mn1);
        m0 = mn0; m1 = mn1;
        l0 *= c0; l1 *= c1;
#pragma unroll
        for (int nt = 0; nt < 16; nt++) {
            out[nt][0] *= c0; out[nt][1] *= c0;
            out[nt][2] *= c1; out[nt][3] *= c1;
        }
#pragma unroll
        for (int nt = 0; nt < 8; nt++) {
            C[nt][0] = __expf(C[nt][0] - m0);
            C[nt][1] = __expf(C[nt][1] - m0);
            C[nt][2] = __expf(C[nt][2] - m1);
            C[nt][3] = __expf(C[nt][3] - m1);
            l0 += C[nt][0] + C[nt][1];
            l1 += C[nt][2] + C[nt][3];
        }

#pragma unroll
        for (int ks = 0; ks < 4; ks++) {
            uint32_t ph[4];
            {
                __half2 hh;
                hh = __floats2half2_rn(C[2 * ks][0], C[2 * ks][1]);
                ph[0] = *(uint32_t*)&hh;
                hh = __floats2half2_rn(C[2 * ks][2], C[2 * ks][3]);
                ph[1] = *(uint32_t*)&hh;
                hh = __floats2half2_rn(C[2 * ks + 1][0], C[2 * ks + 1][1]);
                ph[2] = *(uint32_t*)&hh;
                hh = __floats2half2_rn(C[2 * ks + 1][2], C[2 * ks + 1][3]);
                ph[3] = *(uint32_t*)&hh;
            }
#pragma unroll
            for (int dp = 0; dp < 8; dp++) {
                uint32_t vv[4];
                uint32_t va = vhb + v_off + (uint32_t)ks * 16 * AT_PITCH + dp * 32;
                ldsm_x4_t(vv, va);
                mma16816(out[2 * dp], ph, vv);
                mma16816(out[2 * dp + 1], ph, vv + 2);
            }
        }

        __syncthreads();
        if (it + 2 < iters) {
            load_kv_stage(kvbase + s * KVSTG, Kh_, Vh_, (it + 2) * 64, hd, tid);
            cpa_commit();
        }
    }

    l0 += __shfl_xor_sync(0xffffffffu, l0, 1);
    l0 += __shfl_xor_sync(0xffffffffu, l0, 2);
    l1 += __shfl_xor_sync(0xffffffffu, l1, 1);
    l1 += __shfl_xor_sync(0xffffffffu, l1, 2);
    float i0 = 1.f / l0, i1 = 1.f / l1;
    int r0 = q0 + warp * 16 + (lane >> 2);
    int r1 = r0 + 8;
    int cb = hd * HEAD_DIM + (lane & 3) * 2;
#pragma unroll
    for (int nt = 0; nt < 16; nt++) {
        int col = cb + nt * 8;
        *(__half2*)(Oh + (size_t)r0 * DIM + col) =
            __floats2half2_rn(out[nt][0] * i0, out[nt][1] * i0);
        *(__half2*)(Oh + (size_t)r1 * DIM + col) =
            __floats2half2_rn(out[nt][2] * i1, out[nt][3] * i1);
    }
}

// ---------------- launch (fork-join stream DAG, capture-safe) ----------------
static cudaStream_t g_s1 = nullptr, g_s2 = nullptr;
static cudaEvent_t g_eFork, g_eQW, g_eRW, g_eQKV, g_eP0;

extern "C" void kernel_launch(void* const* d_in, const int* in_sizes, int n_in,
                              void* d_out, int out_size) {
    const float* hidden = (const float*)d_in[0];
    const float* temb = (const float*)d_in[1];
    const float* rope_cos = (const float*)d_in[2];
    const float* rope_sin = (const float*)d_in[3];
    const float* norm_w = (const float*)d_in[4];
    const float* norm_b = (const float*)d_in[5];
    const float* mlp_w = (const float*)d_in[6];
    const float* mlp_b = (const float*)d_in[7];
    const float* q_w = (const float*)d_in[8];
    const float* q_b = (const float*)d_in[9];
    const float* k_w = (const float*)d_in[10];
    const float* k_b = (const float*)d_in[11];
    const float* v_w = (const float*)d_in[12];
    const float* v_b = (const float*)d_in[13];
    const float* rms_q_w = (const float*)d_in[14];
    const float* rms_k_w = (const float*)d_in[15];
    const float* out_w = (const float*)d_in[16];
    const float* out_b = (const float*)d_in[17];
    float* out = (float*)d_out;

    float *emb_p, *bqkv_p, *part_p;
    __half *nh, *wqkv, *wm, *wo, *mlpb, *attnh;
    __half *qh, *kh, *vh;
    cudaGetSymbolAddress((void**)&emb_p, g_emb);
    cudaGetSymbolAddress((void**)&bqkv_p, g_bqkv);
    cudaGetSymbolAddress((void**)&part_p, g_part);
    cudaGetSymbolAddress((void**)&nh, g_nh);
    cudaGetSymbolAddress((void**)&wqkv, g_wqkv);
    cudaGetSymbolAddress((void**)&wm, g_wm);
    cudaGetSymbolAddress((void**)&wo, g_wo);
    cudaGetSymbolAddress((void**)&mlpb, g_mlp);
    cudaGetSymbolAddress((void**)&attnh, g_attnh);
    cudaGetSymbolAddress((void**)&qh, g_qh);
    cudaGetSymbolAddress((void**)&kh, g_kh);
    cudaGetSymbolAddress((void**)&vh, g_vh);

    if (!g_s1) {
        cudaStreamCreateWithFlags(&g_s1, cudaStreamNonBlocking);
        cudaStreamCreateWithFlags(&g_s2, cudaStreamNonBlocking);
        cudaEventCreateWithFlags(&g_eFork, cudaEventDisableTiming);
        cudaEventCreateWithFlags(&g_eQW, cudaEventDisableTiming);
        cudaEventCreateWithFlags(&g_eRW, cudaEventDisableTiming);
        cudaEventCreateWithFlags(&g_eQKV, cudaEventDisableTiming);
        cudaEventCreateWithFlags(&g_eP0, cudaEventDisableTiming);
        cudaFuncSetAttribute(gemm_mma<1>, cudaFuncAttributeMaxDynamicSharedMemorySize, GEMM_SMEM);
        cudaFuncSetAttribute(gemm_mma<3>, cudaFuncAttributeMaxDynamicSharedMemorySize, GEMM_SMEM);
        cudaFuncSetAttribute(gemm_mma<4>, cudaFuncAttributeMaxDynamicSharedMemorySize, GEMM_SMEM);
        cudaFuncSetAttribute(flash_mma, cudaFuncAttributeMaxDynamicSharedMemorySize, FLASH_SMEM);
    }
    cudaStream_t s0 = (cudaStream_t)0;

    // fork: qkv weight conversion on s1 (issued first)
    cudaEventRecord(g_eFork, s0);
    cudaStreamWaitEvent(g_s1, g_eFork, 0);
    cvt_qkv<<<(unsigned)((QKV_W_TOTAL / 8 + 255) / 256), 256, 0, g_s1>>>(
        q_w, k_w, v_w, wqkv, q_b, k_b, v_b, bqkv_p);
    cudaEventRecord(g_eQW, g_s1);

    // main: emb + ln
    emb_gemv<<<3 * DIM, 128, 0, s0>>>(temb, norm_w, norm_b, emb_p);
    ln_mod<<<S_LEN, 256, 0, s0>>>(hidden, emb_p, nh);

    // launch #4: QKV GEMM with fused rmsnorm+rope epilogue (ncu profiles this)
    cudaStreamWaitEvent(s0, g_eQW, 0);
    gemm_mma<4><<<dim3((S_LEN / 128) * (QKV_N / 128), 1), 256, GEMM_SMEM, s0>>>(
        nh, wqkv, S_LEN, DIM, DIM, DIM,
        bqkv_p, nullptr, 0, nullptr, 0,
        rope_cos, rope_sin, rms_q_w, rms_k_w, qh, kh, vh);
    cudaEventRecord(g_eQKV, s0);

    // remaining weight conversion on s1 (runs concurrently with QKV)
    cvt_rest<<<(unsigned)((REST_TOTAL / 8 + 255) / 256), 256, 0, g_s1>>>(
        mlp_w, out_w, wm, wo);
    cudaEventRecord(g_eRW, g_s1);

    // fork: attention chain + out-proj attn-part on s2
    cudaStreamWaitEvent(g_s2, g_eQKV, 0);
    flash_mma<<<dim3(S_LEN / 128, HEADS), 256, FLASH_SMEM, g_s2>>>(qh, kh, vh, attnh);
    cudaStreamWaitEvent(g_s2, g_eRW, 0);
    gemm_mma<3><<<dim3((S_LEN / 128) * (DIM / 128), 1), 256, GEMM_SMEM, g_s2>>>(
        attnh, wo, S_LEN, DIM, DIM, CAT_K,
        nullptr, part_p, DIM, nullptr, 0,
        nullptr, nullptr, nullptr, nullptr, nullptr, nullptr, nullptr);
    cudaEventRecord(g_eP0, g_s2);

    // main: MLP GEMM, then out-proj mlp-part (split-K=3 over K=12288)
    cudaStreamWaitEvent(s0, g_eRW, 0);
    gemm_mma<1><<<dim3((S_LEN / 128) * (MLP_H / 128), 1), 256, GEMM_SMEM, s0>>>(
        nh, wm, S_LEN, DIM, DIM, DIM,
        mlp_b, nullptr, 0, mlpb, MLP_H,
        nullptr, nullptr, nullptr, nullptr, nullptr, nullptr, nullptr);
    gemm_mma<3><<<dim3((S_LEN / 128) * (DIM / 128), 3), 256, GEMM_SMEM, s0>>>(
        mlpb, wo + DIM, S_LEN, MLP_H / 3, MLP_H, CAT_K,
        nullptr, part_p + (size_t)S_LEN * DIM, DIM, nullptr, 0,
        nullptr, nullptr, nullptr, nullptr, nullptr, nullptr, nullptr);

    // join; final reduce + gated residual
    cudaStreamWaitEvent(s0, g_eP0, 0);
    final_reduce<<<(S_LEN * DIM / 4 + 255) / 256, 256, 0, s0>>>(
        part_p, part_p + (size_t)S_LEN * DIM, part_p + 2 * (size_t)S_LEN * DIM,
        part_p + 3 * (size_t)S_LEN * DIM, hidden, emb_p, out_b, out);
}